// round 12
// baseline (speedup 1.0000x reference)
#include <cuda_runtime.h>
#include <math.h>
#include <stdint.h>

// Problem constants
#define Bc 8
#define Tc 512
#define Dc 768
#define Hc 8
#define HDc 96
#define BTc (Bc*Tc)

// ---------------- scratch (device globals; no cudaMalloc allowed) ----------------
__device__ __align__(16) float g_mean[Bc*Dc];
__device__ int   g_idx_s[Bc];
__device__ int   g_idx_t[Bc];
__device__ __align__(16) float g_xns [BTc*Dc];
__device__ __align__(16) float g_xt  [BTc*Dc];
__device__ __align__(16) float g_qkv [BTc*3*Dc];
__device__ __align__(16) float g_qt  [BTc*Dc];
__device__ __align__(16) float g_kt  [BTc*Dc];
__device__ __align__(16) float g_vt  [BTc*Dc];
__device__ __align__(16) float g_att [BTc*Dc];
__device__ __align__(16) float g_att2[BTc*Dc];
__device__ __align__(16) float g_spat[BTc*Dc];
__device__ __align__(16) float g_temp[BTc*Dc];
__device__ __align__(16) float g_cq  [BTc*Dc];
__device__ __align__(16) float g_ckv [BTc*2*Dc];
__device__ __align__(16) float g_x1  [BTc*Dc];
__device__ __align__(16) float g_xm  [BTc*Dc];
__device__ __align__(16) float g_y   [BTc*4*Dc];

__device__ __forceinline__ float gelu_exact(float v) {
    return 0.5f * v * (1.0f + erff(v * 0.70710678118654752f));
}

__device__ __forceinline__ void mma_tf32(float* c, const uint32_t* a, const uint32_t* b) {
    asm volatile(
        "mma.sync.aligned.m16n8k8.row.col.f32.tf32.tf32.f32 "
        "{%0,%1,%2,%3}, {%4,%5,%6,%7}, {%8,%9}, {%0,%1,%2,%3};\n"
        : "+f"(c[0]), "+f"(c[1]), "+f"(c[2]), "+f"(c[3])
        : "r"(a[0]), "r"(a[1]), "r"(a[2]), "r"(a[3]),
          "r"(b[0]), "r"(b[1]));
}

__device__ __forceinline__ void cp16(uint32_t saddr, const void* g) {
    asm volatile("cp.async.cg.shared.global [%0], [%1], 16;" :: "r"(saddr), "l"(g));
}
#define CP_COMMIT() asm volatile("cp.async.commit_group;" ::: "memory")
#define CP_WAIT1()  asm volatile("cp.async.wait_group 1;" ::: "memory")

// ---------------- router part 1: mean over T ----------------
__global__ void rmean_kernel(const float* __restrict__ x, float* __restrict__ mean) {
    int b = blockIdx.x;
    int d = threadIdx.x;            // 768 threads
    float s = 0.f;
    const float* xb = x + (long)b * Tc * Dc + d;
    #pragma unroll 8
    for (int t = 0; t < Tc; t++) s += xb[(long)t * Dc];
    mean[b * Dc + d] = s * (1.0f / (float)Tc);
}

// ---------------- router part 2: MLP -> argmax experts ----------------
__global__ void router_kernel(const float* __restrict__ mean,
                              const float* __restrict__ w1, const float* __restrict__ b1,
                              const float* __restrict__ w2, const float* __restrict__ b2,
                              int* __restrict__ idx_s, int* __restrict__ idx_t) {
    int b = blockIdx.x;
    int j = threadIdx.x;            // 128 threads
    __shared__ float h[128];
    __shared__ float lg[8];
    float a = b1[j];
    const float* mb = mean + b * Dc;
    const float* wr = w1 + j * Dc;
    for (int d = 0; d < Dc; d++) a += mb[d] * wr[d];
    h[j] = gelu_exact(a);
    __syncthreads();
    if (j < 8) {
        float a2 = b2[j];
        const float* wrr = w2 + j * 128;
        for (int i = 0; i < 128; i++) a2 += h[i] * wrr[i];
        lg[j] = a2;
    }
    __syncthreads();
    if (j == 0) {
        int bi = 0;
        for (int i = 1; i < 4; i++) if (lg[i] > lg[bi]) bi = i;
        idx_s[b] = bi;
        int bt = 4;
        for (int i = 5; i < 8; i++) if (lg[i] > lg[bt]) bt = i;
        idx_t[b] = bt - 4;
    }
}

// ---------------- LayerNorm over D=768, one row per block, 2 param sets ------
__global__ __launch_bounds__(256)
void ln2_kernel(const float* __restrict__ x,
                const float* __restrict__ g0, const float* __restrict__ b0,
                float* __restrict__ o0,
                const float* __restrict__ g1, const float* __restrict__ b1,
                float* __restrict__ o1) {
    long row = blockIdx.x;
    const float* g   = blockIdx.y ? g1 : g0;
    const float* bet = blockIdx.y ? b1 : b0;
    float* o         = blockIdx.y ? o1 : o0;
    int tid = threadIdx.x;
    const float* xr = x + row * Dc;
    float v0 = xr[tid], v1 = xr[tid + 256], v2 = xr[tid + 512];
    float s  = v0 + v1 + v2;
    float ss = v0 * v0 + v1 * v1 + v2 * v2;
    #pragma unroll
    for (int off = 16; off > 0; off >>= 1) {
        s  += __shfl_xor_sync(0xffffffffu, s,  off);
        ss += __shfl_xor_sync(0xffffffffu, ss, off);
    }
    __shared__ float rs[8], rss[8];
    int lane = tid & 31, wid = tid >> 5;
    if (lane == 0) { rs[wid] = s; rss[wid] = ss; }
    __syncthreads();
    if (tid == 0) {
        float S = 0.f, SS = 0.f;
        for (int i = 0; i < 8; i++) { S += rs[i]; SS += rss[i]; }
        float mean = S * (1.0f / (float)Dc);
        float var  = SS * (1.0f / (float)Dc) - mean * mean;
        rs[0] = mean;
        rss[0] = rsqrtf(var + 1e-5f);
    }
    __syncthreads();
    float mean = rs[0], inv = rss[0];
    float* orow = o + row * Dc;
    orow[tid]       = (v0 - mean) * inv * g[tid]       + bet[tid];
    orow[tid + 256] = (v1 - mean) * inv * g[tid + 256] + bet[tid + 256];
    orow[tid + 512] = (v2 - mean) * inv * g[tid + 512] + bet[tid + 512];
}

__global__ __launch_bounds__(256)
void ln_kernel(const float* __restrict__ x, const float* __restrict__ g,
               const float* __restrict__ bet, float* __restrict__ o) {
    long row = blockIdx.x;
    int tid = threadIdx.x;
    const float* xr = x + row * Dc;
    float v0 = xr[tid], v1 = xr[tid + 256], v2 = xr[tid + 512];
    float s  = v0 + v1 + v2;
    float ss = v0 * v0 + v1 * v1 + v2 * v2;
    #pragma unroll
    for (int off = 16; off > 0; off >>= 1) {
        s  += __shfl_xor_sync(0xffffffffu, s,  off);
        ss += __shfl_xor_sync(0xffffffffu, ss, off);
    }
    __shared__ float rs[8], rss[8];
    int lane = tid & 31, wid = tid >> 5;
    if (lane == 0) { rs[wid] = s; rss[wid] = ss; }
    __syncthreads();
    if (tid == 0) {
        float S = 0.f, SS = 0.f;
        for (int i = 0; i < 8; i++) { S += rs[i]; SS += rss[i]; }
        float mean = S * (1.0f / (float)Dc);
        float var  = SS * (1.0f / (float)Dc) - mean * mean;
        rs[0] = mean;
        rss[0] = rsqrtf(var + 1e-5f);
    }
    __syncthreads();
    float mean = rs[0], inv = rss[0];
    float* orow = o + row * Dc;
    orow[tid]       = (v0 - mean) * inv * g[tid]       + bet[tid];
    orow[tid + 256] = (v1 - mean) * inv * g[tid + 256] + bet[tid + 256];
    orow[tid + 512] = (v2 - mean) * inv * g[tid + 512] + bet[tid + 512];
}

// ------------- tensor-core GEMM: C = act(A @ W^T + bias) [+ resid] ------------
// TF32 mma.sync m16n8k8, fp32 accumulate, raw-fp32-bit operands.
// cp.async 3-stage pipeline, tiles 128x128x32, 256 threads = 8 warps (2M x 4N).
// __launch_bounds__(256, 2): force <=128 regs -> 2 CTAs/SM (4 warps/SMSP).
// Up to 4 independent "slices" per launch, selected by blockIdx.y range.
struct GArgs {
    const float* A[4];
    const float* W[4];
    const float* bias[4];
    const float* resid[4];
    float* C[4];
    int ldc[4];
    int lda[4];
    long wstride[4];
    const int* eidx[4];
    int yOff[4];
    int nSlices;
    int ldw, bstride;      // bstride < 0 => use ldc[slice] as bias stride
    int Kdim, act;
};

#define GSTAGE_U32 (2 * 128 * 36)
#define GEMM_SMEM  (3 * GSTAGE_U32 * 4)

__global__ __launch_bounds__(256, 2)
void gemm_tc(GArgs g) {
    extern __shared__ uint32_t sm[];
    const uint32_t sb = (uint32_t)__cvta_generic_to_shared(sm);

    const int tid  = threadIdx.x;
    const int wid  = tid >> 5;
    const int lane = tid & 31;
    const int grp  = lane >> 2;        // 0..7
    const int tg   = lane & 3;         // 0..3
    const int warpM = wid & 1;
    const int warpN = wid >> 1;

    const int y = blockIdx.y;
    int slice = 0;
    #pragma unroll
    for (int i = 1; i < 4; i++)
        if (i < g.nSlices && y >= g.yOff[i]) slice = i;
    const int n0 = (y - g.yOff[slice]) * 128;

    const int bz = blockIdx.z;
    const long rowBase = ((long)bz * gridDim.x + blockIdx.x) * 128;

    const int lda = g.lda[slice];
    const int ldc = g.ldc[slice];
    const int bstr = (g.bstride < 0) ? ldc : g.bstride;
    const int e = g.eidx[slice] ? g.eidx[slice][bz] : 0;
    const float* Ab = g.A[slice] + rowBase * lda;
    const float* Wb = g.W[slice] + (long)e * g.wstride[slice] + (long)n0 * g.ldw;
    const float* bb = g.bias[slice] + (long)e * bstr + n0;
    const float* resid = g.resid[slice];
    float* C = g.C[slice];

    float acc[4][4][4];
    #pragma unroll
    for (int i = 0; i < 4; i++)
        #pragma unroll
        for (int j = 0; j < 4; j++)
            #pragma unroll
            for (int r = 0; r < 4; r++) acc[i][j][r] = 0.f;

    const int lrow = tid >> 1;
    const int lcol = (tid & 1) * 16;
    const float* aptr = Ab + (long)lrow * lda + lcol;
    const float* wptr = Wb + (long)lrow * g.ldw + lcol;
    const uint32_t soff = (lrow * 36 + lcol) * 4;

    const int nK = g.Kdim >> 5;

    #pragma unroll
    for (int s = 0; s < 2; s++) {
        uint32_t as = sb + s * (GSTAGE_U32 * 4) + soff;
        uint32_t bs = as + 128 * 36 * 4;
        const float* ap = aptr + s * 32;
        const float* wp = wptr + s * 32;
        #pragma unroll
        for (int q = 0; q < 4; q++) {
            cp16(as + q * 16, ap + q * 4);
            cp16(bs + q * 16, wp + q * 4);
        }
        CP_COMMIT();
    }

    for (int kt = 0; kt < nK; kt++) {
        CP_WAIT1();
        __syncthreads();

        const int nt = kt + 2;
        if (nt < nK) {
            const int s = nt % 3;
            uint32_t as = sb + s * (GSTAGE_U32 * 4) + soff;
            uint32_t bs = as + 128 * 36 * 4;
            const float* ap = aptr + nt * 32;
            const float* wp = wptr + nt * 32;
            #pragma unroll
            for (int q = 0; q < 4; q++) {
                cp16(as + q * 16, ap + q * 4);
                cp16(bs + q * 16, wp + q * 4);
            }
        }
        CP_COMMIT();

        const uint32_t* Asb = sm + (kt % 3) * GSTAGE_U32;
        const uint32_t* Bsb = Asb + 128 * 36;

        #pragma unroll
        for (int kk = 0; kk < 4; kk++) {
            const int k = kk * 8 + tg;
            uint32_t afr[4][4];
            #pragma unroll
            for (int i = 0; i < 4; i++) {
                const int m = warpM * 64 + i * 16 + grp;
                afr[i][0] = Asb[m * 36 + k];
                afr[i][1] = Asb[(m + 8) * 36 + k];
                afr[i][2] = Asb[m * 36 + k + 4];
                afr[i][3] = Asb[(m + 8) * 36 + k + 4];
            }
            uint32_t bfr[4][2];
            #pragma unroll
            for (int j = 0; j < 4; j++) {
                const int n = warpN * 32 + j * 8 + grp;
                bfr[j][0] = Bsb[n * 36 + k];
                bfr[j][1] = Bsb[n * 36 + k + 4];
            }
            #pragma unroll
            for (int i = 0; i < 4; i++)
                #pragma unroll
                for (int j = 0; j < 4; j++)
                    mma_tf32(acc[i][j], afr[i], bfr[j]);
        }
    }

    #pragma unroll
    for (int i = 0; i < 4; i++) {
        const long m0 = rowBase + warpM * 64 + i * 16 + grp;
        #pragma unroll
        for (int j = 0; j < 4; j++) {
            const int coff = warpN * 32 + j * 8 + 2 * tg;
            const int col = n0 + coff;
            #pragma unroll
            for (int rr = 0; rr < 2; rr++) {
                const long row = m0 + rr * 8;
                float v0 = acc[i][j][rr * 2 + 0] + bb[coff];
                float v1 = acc[i][j][rr * 2 + 1] + bb[coff + 1];
                if (g.act == 1) { v0 = gelu_exact(v0); v1 = gelu_exact(v1); }
                if (resid) {
                    const float* rp = resid + row * ldc + col;
                    v0 += rp[0]; v1 += rp[1];
                }
                *(float2*)(C + row * ldc + col) = make_float2(v0, v1);
            }
        }
    }
}

// ---------- tensor-core flash attention: 64 Q-rows/CTA, 64-col KV tiles ----------
struct AArgs {
    const float* Q[2]; const float* K[2]; const float* V[2];
    float* O[2];
    int ldq[2], ldk[2], ldv[2], ldo[2], causal[2];
};
#define AT_LD  104
#define AT_LDP 72
#define ATT_SMEM ((3*64*AT_LD + 64*AT_LDP) * 4)
__global__ __launch_bounds__(128)
void attn_tc(AArgs ar) {
    extern __shared__ uint32_t asm_[];
    uint32_t* Qs = asm_;
    uint32_t* Ks = asm_ + 64 * AT_LD;
    uint32_t* Vs = asm_ + 2 * 64 * AT_LD;
    uint32_t* Ps = asm_ + 3 * 64 * AT_LD;

    const int tid  = threadIdx.x;
    const int lane = tid & 31;
    const int w    = tid >> 5;
    const int grp  = lane >> 2;
    const int tg   = lane & 3;
    const int which = blockIdx.x >> 3;
    const int qt = blockIdx.x & 7;
    const int h  = blockIdx.y;
    const int b  = blockIdx.z;
    const float scale = 0.1020620726159658f;   // 1/sqrt(96)

    const int ldq = ar.ldq[which], ldk = ar.ldk[which], ldv = ar.ldv[which], ldo = ar.ldo[which];
    const int causal = ar.causal[which];
    const float* Qb = ar.Q[which] + ((long)b * Tc + qt * 64) * ldq + h * HDc;
    const float* Kb = ar.K[which] + (long)b * Tc * ldk + h * HDc;
    const float* Vb = ar.V[which] + (long)b * Tc * ldv + h * HDc;

    for (int i = tid; i < 64 * 24; i += 128) {
        int r = i / 24, c = (i % 24) * 4;
        *(uint4*)&Qs[r * AT_LD + c] = *(const uint4*)(Qb + (long)r * ldq + c);
    }

    float m_lo = -1e30f, m_hi = -1e30f, l_lo = 0.f, l_hi = 0.f;
    float oacc[12][4];
    #pragma unroll
    for (int d = 0; d < 12; d++)
        #pragma unroll
        for (int r = 0; r < 4; r++) oacc[d][r] = 0.f;

    const int m0 = w * 16 + grp;
    const int rowg_lo = qt * 64 + m0;
    const int rowg_hi = rowg_lo + 8;

    const int ktmax = causal ? qt : (Tc / 64 - 1);
    for (int kt = 0; kt <= ktmax; kt++) {
        __syncthreads();
        for (int i = tid; i < 64 * 24; i += 128) {
            int r = i / 24, c = (i % 24) * 4;
            *(uint4*)&Ks[r * AT_LD + c] = *(const uint4*)(Kb + (long)(kt * 64 + r) * ldk + c);
            *(uint4*)&Vs[r * AT_LD + c] = *(const uint4*)(Vb + (long)(kt * 64 + r) * ldv + c);
        }
        __syncthreads();

        float sacc[8][4];
        #pragma unroll
        for (int j = 0; j < 8; j++)
            #pragma unroll
            for (int r = 0; r < 4; r++) sacc[j][r] = 0.f;

        #pragma unroll
        for (int kk = 0; kk < 12; kk++) {
            const int k = kk * 8 + tg;
            uint32_t a[4];
            a[0] = Qs[m0 * AT_LD + k];
            a[1] = Qs[(m0 + 8) * AT_LD + k];
            a[2] = Qs[m0 * AT_LD + k + 4];
            a[3] = Qs[(m0 + 8) * AT_LD + k + 4];
            #pragma unroll
            for (int j = 0; j < 8; j++) {
                uint32_t bf[2];
                const int n = j * 8 + grp;
                bf[0] = Ks[n * AT_LD + k];
                bf[1] = Ks[n * AT_LD + k + 4];
                mma_tf32(sacc[j], a, bf);
            }
        }

        const bool dmask = causal && (kt == qt);
        float mt_lo = -1e30f, mt_hi = -1e30f;
        #pragma unroll
        for (int j = 0; j < 8; j++) {
            const int c = kt * 64 + j * 8 + 2 * tg;
            float s0 = sacc[j][0] * scale;
            float s1 = sacc[j][1] * scale;
            float s2 = sacc[j][2] * scale;
            float s3 = sacc[j][3] * scale;
            if (dmask) {
                if (c     > rowg_lo) s0 = -1e30f;
                if (c + 1 > rowg_lo) s1 = -1e30f;
                if (c     > rowg_hi) s2 = -1e30f;
                if (c + 1 > rowg_hi) s3 = -1e30f;
            }
            sacc[j][0] = s0; sacc[j][1] = s1; sacc[j][2] = s2; sacc[j][3] = s3;
            mt_lo = fmaxf(mt_lo, fmaxf(s0, s1));
            mt_hi = fmaxf(mt_hi, fmaxf(s2, s3));
        }
        mt_lo = fmaxf(mt_lo, __shfl_xor_sync(0xffffffffu, mt_lo, 1));
        mt_lo = fmaxf(mt_lo, __shfl_xor_sync(0xffffffffu, mt_lo, 2));
        mt_hi = fmaxf(mt_hi, __shfl_xor_sync(0xffffffffu, mt_hi, 1));
        mt_hi = fmaxf(mt_hi, __shfl_xor_sync(0xffffffffu, mt_hi, 2));

        const float mn_lo = fmaxf(m_lo, mt_lo);
        const float mn_hi = fmaxf(m_hi, mt_hi);
        const float al_lo = __expf(m_lo - mn_lo);
        const float al_hi = __expf(m_hi - mn_hi);

        float ps_lo = 0.f, ps_hi = 0.f;
        #pragma unroll
        for (int j = 0; j < 8; j++) {
            const int c = j * 8 + 2 * tg;
            float p0 = __expf(sacc[j][0] - mn_lo);
            float p1 = __expf(sacc[j][1] - mn_lo);
            float p2 = __expf(sacc[j][2] - mn_hi);
            float p3 = __expf(sacc[j][3] - mn_hi);
            ps_lo += p0 + p1;
            ps_hi += p2 + p3;
            Ps[m0 * AT_LDP + c]           = __float_as_uint(p0);
            Ps[m0 * AT_LDP + c + 1]       = __float_as_uint(p1);
            Ps[(m0 + 8) * AT_LDP + c]     = __float_as_uint(p2);
            Ps[(m0 + 8) * AT_LDP + c + 1] = __float_as_uint(p3);
        }
        ps_lo += __shfl_xor_sync(0xffffffffu, ps_lo, 1);
        ps_lo += __shfl_xor_sync(0xffffffffu, ps_lo, 2);
        ps_hi += __shfl_xor_sync(0xffffffffu, ps_hi, 1);
        ps_hi += __shfl_xor_sync(0xffffffffu, ps_hi, 2);

        l_lo = l_lo * al_lo + ps_lo;  m_lo = mn_lo;
        l_hi = l_hi * al_hi + ps_hi;  m_hi = mn_hi;
        #pragma unroll
        for (int d = 0; d < 12; d++) {
            oacc[d][0] *= al_lo; oacc[d][1] *= al_lo;
            oacc[d][2] *= al_hi; oacc[d][3] *= al_hi;
        }
        __syncwarp();

        #pragma unroll
        for (int kc = 0; kc < 8; kc++) {
            const int k = kc * 8 + tg;
            uint32_t a[4];
            a[0] = Ps[m0 * AT_LDP + k];
            a[1] = Ps[(m0 + 8) * AT_LDP + k];
            a[2] = Ps[m0 * AT_LDP + k + 4];
            a[3] = Ps[(m0 + 8) * AT_LDP + k + 4];
            #pragma unroll
            for (int d = 0; d < 12; d++) {
                uint32_t bf[2];
                const int n = d * 8 + grp;
                bf[0] = Vs[k * AT_LD + n];
                bf[1] = Vs[(k + 4) * AT_LD + n];
                mma_tf32(oacc[d], a, bf);
            }
        }
    }

    const float inv_lo = 1.0f / l_lo;
    const float inv_hi = 1.0f / l_hi;
    float* Ob = ar.O[which] + ((long)b * Tc + qt * 64 + w * 16) * ldo + h * HDc;
    #pragma unroll
    for (int d = 0; d < 12; d++) {
        const int c = d * 8 + 2 * tg;
        *(float2*)(Ob + (long)grp * ldo + c) =
            make_float2(oacc[d][0] * inv_lo, oacc[d][1] * inv_lo);
        *(float2*)(Ob + (long)(grp + 8) * ldo + c) =
            make_float2(oacc[d][2] * inv_hi, oacc[d][3] * inv_hi);
    }
}

// ---------------- host driver ----------------
static GArgs mkargs() {
    GArgs g;
    for (int i = 0; i < 4; i++) {
        g.A[i]=0; g.W[i]=0; g.bias[i]=0; g.resid[i]=0; g.C[i]=0;
        g.ldc[i]=0; g.lda[i]=0; g.wstride[i]=0; g.eidx[i]=0; g.yOff[i]=0;
    }
    g.nSlices=1; g.ldw=0; g.bstride=0; g.Kdim=0; g.act=0;
    return g;
}

extern "C" void kernel_launch(void* const* d_in, const int* in_sizes, int n_in,
                              void* d_out, int out_size) {
    (void)in_sizes; (void)n_in; (void)out_size;
    const float* x       = (const float*)d_in[0];
    const float* r_w1    = (const float*)d_in[1];
    const float* r_b1    = (const float*)d_in[2];
    const float* r_w2    = (const float*)d_in[3];
    const float* r_b2    = (const float*)d_in[4];
    const float* ns_g    = (const float*)d_in[5];
    const float* ns_b    = (const float*)d_in[6];
    const float* nt_g    = (const float*)d_in[7];
    const float* nt_b    = (const float*)d_in[8];
    const float* nm_g    = (const float*)d_in[9];
    const float* nm_b    = (const float*)d_in[10];
    const float* sp_wqkv = (const float*)d_in[11];
    const float* sp_bqkv = (const float*)d_in[12];
    const float* sp_wo   = (const float*)d_in[13];
    const float* sp_bo   = (const float*)d_in[14];
    const float* tp_wq   = (const float*)d_in[15];
    const float* tp_bq   = (const float*)d_in[16];
    const float* tp_wk   = (const float*)d_in[17];
    const float* tp_bk   = (const float*)d_in[18];
    const float* tp_wv   = (const float*)d_in[19];
    const float* tp_bv   = (const float*)d_in[20];
    const float* tp_wo   = (const float*)d_in[21];
    const float* tp_bo   = (const float*)d_in[22];
    const float* c_wqkv  = (const float*)d_in[23];
    const float* c_bqkv  = (const float*)d_in[24];
    const float* c_wo    = (const float*)d_in[25];
    const float* c_bo    = (const float*)d_in[26];
    const float* m_w1    = (const float*)d_in[27];
    const float* m_b1    = (const float*)d_in[28];
    const float* m_w2    = (const float*)d_in[29];
    const float* m_b2    = (const float*)d_in[30];
    float* out = (float*)d_out;

    float *mean, *xns, *xt, *qkv, *qt, *kt, *vt, *att, *att2, *spat, *temp, *cq, *ckv, *x1, *xm, *y;
    int *idx_s, *idx_t;
    cudaGetSymbolAddress((void**)&mean,  g_mean);
    cudaGetSymbolAddress((void**)&idx_s, g_idx_s);
    cudaGetSymbolAddress((void**)&idx_t, g_idx_t);
    cudaGetSymbolAddress((void**)&xns,   g_xns);
    cudaGetSymbolAddress((void**)&xt,    g_xt);
    cudaGetSymbolAddress((void**)&qkv,   g_qkv);
    cudaGetSymbolAddress((void**)&qt,    g_qt);
    cudaGetSymbolAddress((void**)&kt,    g_kt);
    cudaGetSymbolAddress((void**)&vt,    g_vt);
    cudaGetSymbolAddress((void**)&att,   g_att);
    cudaGetSymbolAddress((void**)&att2,  g_att2);
    cudaGetSymbolAddress((void**)&spat,  g_spat);
    cudaGetSymbolAddress((void**)&temp,  g_temp);
    cudaGetSymbolAddress((void**)&cq,    g_cq);
    cudaGetSymbolAddress((void**)&ckv,   g_ckv);
    cudaGetSymbolAddress((void**)&x1,    g_x1);
    cudaGetSymbolAddress((void**)&xm,    g_xm);
    cudaGetSymbolAddress((void**)&y,     g_y);

    cudaFuncSetAttribute(gemm_tc, cudaFuncAttributeMaxDynamicSharedMemorySize, GEMM_SMEM);
    cudaFuncSetAttribute(attn_tc, cudaFuncAttributeMaxDynamicSharedMemorySize, ATT_SMEM);

    rmean_kernel<<<Bc, Dc>>>(x, mean);
    router_kernel<<<Bc, 128>>>(mean, r_w1, r_b1, r_w2, r_b2, idx_s, idx_t);

    ln2_kernel<<<dim3(BTc, 2), 256>>>(x, ns_g, ns_b, xns, nt_g, nt_b, xt);

    // ---- spatial qkv + temporal q/k/v fused (4 slices, 36 y-blocks) ----
    {
        GArgs a = mkargs();
        a.A[0] = xns; a.W[0] = sp_wqkv; a.bias[0] = sp_bqkv; a.C[0] = qkv; a.ldc[0] = 3 * Dc;
        a.wstride[0] = (long)3 * Dc * Dc; a.eidx[0] = idx_s; a.lda[0] = Dc; a.yOff[0] = 0;
        a.A[1] = xt; a.W[1] = tp_wq; a.bias[1] = tp_bq; a.C[1] = qt; a.ldc[1] = Dc;
        a.wstride[1] = (long)Dc * Dc; a.eidx[1] = idx_t; a.lda[1] = Dc; a.yOff[1] = 18;
        a.A[2] = xt; a.W[2] = tp_wk; a.bias[2] = tp_bk; a.C[2] = kt; a.ldc[2] = Dc;
        a.wstride[2] = (long)Dc * Dc; a.eidx[2] = idx_t; a.lda[2] = Dc; a.yOff[2] = 24;
        a.A[3] = xt; a.W[3] = tp_wv; a.bias[3] = tp_bv; a.C[3] = vt; a.ldc[3] = Dc;
        a.wstride[3] = (long)Dc * Dc; a.eidx[3] = idx_t; a.lda[3] = Dc; a.yOff[3] = 30;
        a.nSlices = 4; a.ldw = Dc;
        a.bstride = -1;   // bias stride = ldc[slice] (3*Dc spatial, Dc temporal)
        a.Kdim = Dc; a.act = 0;
        gemm_tc<<<dim3(4, 36, 8), 256, GEMM_SMEM>>>(a);
    }

    // ---- both flash attentions in one launch ----
    {
        AArgs ar;
        ar.Q[0] = qkv;      ar.K[0] = qkv + Dc; ar.V[0] = qkv + 2 * Dc; ar.O[0] = att;
        ar.ldq[0] = 3 * Dc; ar.ldk[0] = 3 * Dc; ar.ldv[0] = 3 * Dc;     ar.ldo[0] = Dc; ar.causal[0] = 0;
        ar.Q[1] = qt;       ar.K[1] = kt;       ar.V[1] = vt;           ar.O[1] = att2;
        ar.ldq[1] = Dc;     ar.ldk[1] = Dc;     ar.ldv[1] = Dc;         ar.ldo[1] = Dc; ar.causal[1] = 1;
        attn_tc<<<dim3(16, 8, 8), 128, ATT_SMEM>>>(ar);
    }

    // ---- both Wo projections in one launch ----
    {
        GArgs a = mkargs();
        a.A[0] = att;  a.W[0] = sp_wo; a.bias[0] = sp_bo; a.C[0] = spat; a.ldc[0] = Dc;
        a.wstride[0] = (long)Dc * Dc; a.eidx[0] = idx_s; a.lda[0] = Dc; a.yOff[0] = 0;
        a.A[1] = att2; a.W[1] = tp_wo; a.bias[1] = tp_bo; a.C[1] = temp; a.ldc[1] = Dc;
        a.wstride[1] = (long)Dc * Dc; a.eidx[1] = idx_t; a.lda[1] = Dc; a.yOff[1] = 6;
        a.resid[1] = xt;
        a.nSlices = 2; a.ldw = Dc; a.bstride = Dc; a.Kdim = Dc; a.act = 0;
        gemm_tc<<<dim3(4, 12, 8), 256, GEMM_SMEM>>>(a);
    }

    // ---- cross qkv fused ----
    {
        GArgs a = mkargs();
        a.A[0] = spat; a.W[0] = c_wqkv;               a.bias[0] = c_bqkv;          a.C[0] = cq;       a.ldc[0] = Dc;     a.lda[0] = Dc; a.yOff[0] = 0;
        a.A[1] = temp; a.W[1] = c_wqkv + Dc * Dc;     a.bias[1] = c_bqkv + Dc;     a.C[1] = ckv;      a.ldc[1] = 2 * Dc; a.lda[1] = Dc; a.yOff[1] = 6;
        a.A[2] = temp; a.W[2] = c_wqkv + 2 * Dc * Dc; a.bias[2] = c_bqkv + 2 * Dc; a.C[2] = ckv + Dc; a.ldc[2] = 2 * Dc; a.lda[2] = Dc; a.yOff[2] = 12;
        a.nSlices = 3; a.ldw = Dc; a.bstride = 0; a.Kdim = Dc; a.act = 0;
        gemm_tc<<<dim3(32, 18, 1), 256, GEMM_SMEM>>>(a);
    }
    {
        AArgs ar;
        ar.Q[0] = cq;   ar.K[0] = ckv;      ar.V[0] = ckv + Dc;  ar.O[0] = att;
        ar.ldq[0] = Dc; ar.ldk[0] = 2 * Dc; ar.ldv[0] = 2 * Dc;  ar.ldo[0] = Dc; ar.causal[0] = 0;
        ar.Q[1] = cq;   ar.K[1] = ckv;      ar.V[1] = ckv + Dc;  ar.O[1] = att;
        ar.ldq[1] = Dc; ar.ldk[1] = 2 * Dc; ar.ldv[1] = 2 * Dc;  ar.ldo[1] = Dc; ar.causal[1] = 0;
        attn_tc<<<dim3(8, 8, 8), 128, ATT_SMEM>>>(ar);
    }
    {
        GArgs a = mkargs();
        a.A[0] = att; a.W[0] = c_wo; a.bias[0] = c_bo; a.C[0] = x1; a.ldc[0] = Dc;
        a.lda[0] = Dc; a.resid[0] = x;
        a.nSlices = 1; a.ldw = Dc; a.bstride = 0; a.Kdim = Dc; a.act = 0;
        gemm_tc<<<dim3(32, 6, 1), 256, GEMM_SMEM>>>(a);
    }

    // ---- MLP with residual ----
    ln_kernel<<<BTc, 256>>>(x1, nm_g, nm_b, xm);
    {
        GArgs a = mkargs();
        a.A[0] = xm; a.W[0] = m_w1; a.bias[0] = m_b1; a.C[0] = y; a.ldc[0] = 4 * Dc;
        a.lda[0] = Dc;
        a.nSlices = 1; a.ldw = Dc; a.bstride = 0; a.Kdim = Dc; a.act = 1;
        gemm_tc<<<dim3(32, 24, 1), 256, GEMM_SMEM>>>(a);
    }
    {
        GArgs a = mkargs();
        a.A[0] = y; a.W[0] = m_w2; a.bias[0] = m_b2; a.C[0] = out; a.ldc[0] = Dc;
        a.lda[0] = 4 * Dc; a.resid[0] = x1;
        a.nSlices = 1; a.ldw = 4 * Dc; a.bstride = 0; a.Kdim = 4 * Dc; a.act = 0;
        gemm_tc<<<dim3(32, 6, 1), 256, GEMM_SMEM>>>(a);
    }
}

// round 13
// speedup vs baseline: 1.0018x; 1.0018x over previous
#include <cuda_runtime.h>
#include <math.h>
#include <stdint.h>

// Problem constants
#define Bc 8
#define Tc 512
#define Dc 768
#define Hc 8
#define HDc 96
#define BTc (Bc*Tc)

// ---------------- scratch (device globals; no cudaMalloc allowed) ----------------
__device__ __align__(16) float g_mean[Bc*Dc];
__device__ int   g_idx_s[Bc];
__device__ int   g_idx_t[Bc];
__device__ __align__(16) float g_xns [BTc*Dc];
__device__ __align__(16) float g_xt  [BTc*Dc];
__device__ __align__(16) float g_qkv [BTc*3*Dc];
__device__ __align__(16) float g_qt  [BTc*Dc];
__device__ __align__(16) float g_kt  [BTc*Dc];
__device__ __align__(16) float g_vt  [BTc*Dc];
__device__ __align__(16) float g_att [BTc*Dc];
__device__ __align__(16) float g_att2[BTc*Dc];
__device__ __align__(16) float g_spat[BTc*Dc];
__device__ __align__(16) float g_temp[BTc*Dc];
__device__ __align__(16) float g_cq  [BTc*Dc];
__device__ __align__(16) float g_ckv [BTc*2*Dc];
__device__ __align__(16) float g_x1  [BTc*Dc];
__device__ __align__(16) float g_xm  [BTc*Dc];
__device__ __align__(16) float g_y   [BTc*4*Dc];

__device__ __forceinline__ float gelu_exact(float v) {
    return 0.5f * v * (1.0f + erff(v * 0.70710678118654752f));
}

__device__ __forceinline__ void mma_tf32(float* c, const uint32_t* a, const uint32_t* b) {
    asm volatile(
        "mma.sync.aligned.m16n8k8.row.col.f32.tf32.tf32.f32 "
        "{%0,%1,%2,%3}, {%4,%5,%6,%7}, {%8,%9}, {%0,%1,%2,%3};\n"
        : "+f"(c[0]), "+f"(c[1]), "+f"(c[2]), "+f"(c[3])
        : "r"(a[0]), "r"(a[1]), "r"(a[2]), "r"(a[3]),
          "r"(b[0]), "r"(b[1]));
}

__device__ __forceinline__ void cp16(uint32_t saddr, const void* g) {
    asm volatile("cp.async.cg.shared.global [%0], [%1], 16;" :: "r"(saddr), "l"(g));
}
#define CP_COMMIT() asm volatile("cp.async.commit_group;" ::: "memory")
#define CP_WAIT1()  asm volatile("cp.async.wait_group 1;" ::: "memory")

// ---------------- router part 1: mean over T ----------------
__global__ void rmean_kernel(const float* __restrict__ x, float* __restrict__ mean) {
    int b = blockIdx.x;
    int d = threadIdx.x;            // 768 threads
    float s = 0.f;
    const float* xb = x + (long)b * Tc * Dc + d;
    #pragma unroll 8
    for (int t = 0; t < Tc; t++) s += xb[(long)t * Dc];
    mean[b * Dc + d] = s * (1.0f / (float)Tc);
}

// ---------------- router part 2: MLP -> argmax experts ----------------
__global__ void router_kernel(const float* __restrict__ mean,
                              const float* __restrict__ w1, const float* __restrict__ b1,
                              const float* __restrict__ w2, const float* __restrict__ b2,
                              int* __restrict__ idx_s, int* __restrict__ idx_t) {
    int b = blockIdx.x;
    int j = threadIdx.x;            // 128 threads
    __shared__ float h[128];
    __shared__ float lg[8];
    float a = b1[j];
    const float* mb = mean + b * Dc;
    const float* wr = w1 + j * Dc;
    for (int d = 0; d < Dc; d++) a += mb[d] * wr[d];
    h[j] = gelu_exact(a);
    __syncthreads();
    if (j < 8) {
        float a2 = b2[j];
        const float* wrr = w2 + j * 128;
        for (int i = 0; i < 128; i++) a2 += h[i] * wrr[i];
        lg[j] = a2;
    }
    __syncthreads();
    if (j == 0) {
        int bi = 0;
        for (int i = 1; i < 4; i++) if (lg[i] > lg[bi]) bi = i;
        idx_s[b] = bi;
        int bt = 4;
        for (int i = 5; i < 8; i++) if (lg[i] > lg[bt]) bt = i;
        idx_t[b] = bt - 4;
    }
}

// ---------------- LayerNorm over D=768, one row per block, 2 param sets ------
__global__ __launch_bounds__(256)
void ln2_kernel(const float* __restrict__ x,
                const float* __restrict__ g0, const float* __restrict__ b0,
                float* __restrict__ o0,
                const float* __restrict__ g1, const float* __restrict__ b1,
                float* __restrict__ o1) {
    long row = blockIdx.x;
    const float* g   = blockIdx.y ? g1 : g0;
    const float* bet = blockIdx.y ? b1 : b0;
    float* o         = blockIdx.y ? o1 : o0;
    int tid = threadIdx.x;
    const float* xr = x + row * Dc;
    float v0 = xr[tid], v1 = xr[tid + 256], v2 = xr[tid + 512];
    float s  = v0 + v1 + v2;
    float ss = v0 * v0 + v1 * v1 + v2 * v2;
    #pragma unroll
    for (int off = 16; off > 0; off >>= 1) {
        s  += __shfl_xor_sync(0xffffffffu, s,  off);
        ss += __shfl_xor_sync(0xffffffffu, ss, off);
    }
    __shared__ float rs[8], rss[8];
    int lane = tid & 31, wid = tid >> 5;
    if (lane == 0) { rs[wid] = s; rss[wid] = ss; }
    __syncthreads();
    if (tid == 0) {
        float S = 0.f, SS = 0.f;
        for (int i = 0; i < 8; i++) { S += rs[i]; SS += rss[i]; }
        float mean = S * (1.0f / (float)Dc);
        float var  = SS * (1.0f / (float)Dc) - mean * mean;
        rs[0] = mean;
        rss[0] = rsqrtf(var + 1e-5f);
    }
    __syncthreads();
    float mean = rs[0], inv = rss[0];
    float* orow = o + row * Dc;
    orow[tid]       = (v0 - mean) * inv * g[tid]       + bet[tid];
    orow[tid + 256] = (v1 - mean) * inv * g[tid + 256] + bet[tid + 256];
    orow[tid + 512] = (v2 - mean) * inv * g[tid + 512] + bet[tid + 512];
}

__global__ __launch_bounds__(256)
void ln_kernel(const float* __restrict__ x, const float* __restrict__ g,
               const float* __restrict__ bet, float* __restrict__ o) {
    long row = blockIdx.x;
    int tid = threadIdx.x;
    const float* xr = x + row * Dc;
    float v0 = xr[tid], v1 = xr[tid + 256], v2 = xr[tid + 512];
    float s  = v0 + v1 + v2;
    float ss = v0 * v0 + v1 * v1 + v2 * v2;
    #pragma unroll
    for (int off = 16; off > 0; off >>= 1) {
        s  += __shfl_xor_sync(0xffffffffu, s,  off);
        ss += __shfl_xor_sync(0xffffffffu, ss, off);
    }
    __shared__ float rs[8], rss[8];
    int lane = tid & 31, wid = tid >> 5;
    if (lane == 0) { rs[wid] = s; rss[wid] = ss; }
    __syncthreads();
    if (tid == 0) {
        float S = 0.f, SS = 0.f;
        for (int i = 0; i < 8; i++) { S += rs[i]; SS += rss[i]; }
        float mean = S * (1.0f / (float)Dc);
        float var  = SS * (1.0f / (float)Dc) - mean * mean;
        rs[0] = mean;
        rss[0] = rsqrtf(var + 1e-5f);
    }
    __syncthreads();
    float mean = rs[0], inv = rss[0];
    float* orow = o + row * Dc;
    orow[tid]       = (v0 - mean) * inv * g[tid]       + bet[tid];
    orow[tid + 256] = (v1 - mean) * inv * g[tid + 256] + bet[tid + 256];
    orow[tid + 512] = (v2 - mean) * inv * g[tid + 512] + bet[tid + 512];
}

// ------------- tensor-core GEMM: C = act(A @ W^T + bias) [+ resid] ------------
// TF32 mma.sync m16n8k8, fp32 accumulate, raw-fp32-bit operands.
// cp.async 3-stage smem pipeline + register double-buffered fragments.
// Tiles 128x128x32, 256 threads = 8 warps (2M x 4N). Regs unconstrained
// (cutlass-style high-ILP config; ~1 CTA/SM).
struct GArgs {
    const float* A[4];
    const float* W[4];
    const float* bias[4];
    const float* resid[4];
    float* C[4];
    int ldc[4];
    int lda[4];
    long wstride[4];
    const int* eidx[4];
    int yOff[4];
    int nSlices;
    int ldw, bstride;      // bstride < 0 => use ldc[slice] as bias stride
    int Kdim, act;
};

#define GSTAGE_U32 (2 * 128 * 36)
#define GEMM_SMEM  (3 * GSTAGE_U32 * 4)

__global__ __launch_bounds__(256)
void gemm_tc(GArgs g) {
    extern __shared__ uint32_t sm[];
    const uint32_t sb = (uint32_t)__cvta_generic_to_shared(sm);

    const int tid  = threadIdx.x;
    const int wid  = tid >> 5;
    const int lane = tid & 31;
    const int grp  = lane >> 2;        // 0..7
    const int tg   = lane & 3;         // 0..3
    const int warpM = wid & 1;
    const int warpN = wid >> 1;

    const int y = blockIdx.y;
    int slice = 0;
    #pragma unroll
    for (int i = 1; i < 4; i++)
        if (i < g.nSlices && y >= g.yOff[i]) slice = i;
    const int n0 = (y - g.yOff[slice]) * 128;

    const int bz = blockIdx.z;
    const long rowBase = ((long)bz * gridDim.x + blockIdx.x) * 128;

    const int lda = g.lda[slice];
    const int ldc = g.ldc[slice];
    const int bstr = (g.bstride < 0) ? ldc : g.bstride;
    const int e = g.eidx[slice] ? g.eidx[slice][bz] : 0;
    const float* Ab = g.A[slice] + rowBase * lda;
    const float* Wb = g.W[slice] + (long)e * g.wstride[slice] + (long)n0 * g.ldw;
    const float* bb = g.bias[slice] + (long)e * bstr + n0;
    const float* resid = g.resid[slice];
    float* C = g.C[slice];

    float acc[4][4][4];
    #pragma unroll
    for (int i = 0; i < 4; i++)
        #pragma unroll
        for (int j = 0; j < 4; j++)
            #pragma unroll
            for (int r = 0; r < 4; r++) acc[i][j][r] = 0.f;

    const int lrow = tid >> 1;
    const int lcol = (tid & 1) * 16;
    const float* aptr = Ab + (long)lrow * lda + lcol;
    const float* wptr = Wb + (long)lrow * g.ldw + lcol;
    const uint32_t soff = (lrow * 36 + lcol) * 4;

    const int nK = g.Kdim >> 5;

    #pragma unroll
    for (int s = 0; s < 2; s++) {
        uint32_t as = sb + s * (GSTAGE_U32 * 4) + soff;
        uint32_t bs = as + 128 * 36 * 4;
        const float* ap = aptr + s * 32;
        const float* wp = wptr + s * 32;
        #pragma unroll
        for (int q = 0; q < 4; q++) {
            cp16(as + q * 16, ap + q * 4);
            cp16(bs + q * 16, wp + q * 4);
        }
        CP_COMMIT();
    }

    // register double-buffered fragments
    uint32_t afr[2][4][4];
    uint32_t bfr[2][4][2];

    for (int kt = 0; kt < nK; kt++) {
        CP_WAIT1();
        __syncthreads();

        const int nt = kt + 2;
        if (nt < nK) {
            const int s = nt % 3;
            uint32_t as = sb + s * (GSTAGE_U32 * 4) + soff;
            uint32_t bs = as + 128 * 36 * 4;
            const float* ap = aptr + nt * 32;
            const float* wp = wptr + nt * 32;
            #pragma unroll
            for (int q = 0; q < 4; q++) {
                cp16(as + q * 16, ap + q * 4);
                cp16(bs + q * 16, wp + q * 4);
            }
        }
        CP_COMMIT();

        const uint32_t* Asb = sm + (kt % 3) * GSTAGE_U32;
        const uint32_t* Bsb = Asb + 128 * 36;

        // preload fragments for kk=0
        {
            const int k = tg;
            #pragma unroll
            for (int i = 0; i < 4; i++) {
                const int m = warpM * 64 + i * 16 + grp;
                afr[0][i][0] = Asb[m * 36 + k];
                afr[0][i][1] = Asb[(m + 8) * 36 + k];
                afr[0][i][2] = Asb[m * 36 + k + 4];
                afr[0][i][3] = Asb[(m + 8) * 36 + k + 4];
            }
            #pragma unroll
            for (int j = 0; j < 4; j++) {
                const int n = warpN * 32 + j * 8 + grp;
                bfr[0][j][0] = Bsb[n * 36 + k];
                bfr[0][j][1] = Bsb[n * 36 + k + 4];
            }
        }

        #pragma unroll
        for (int kk = 0; kk < 4; kk++) {
            const int cur = kk & 1;
            if (kk < 3) {
                const int k = (kk + 1) * 8 + tg;
                const int nxt = cur ^ 1;
                #pragma unroll
                for (int i = 0; i < 4; i++) {
                    const int m = warpM * 64 + i * 16 + grp;
                    afr[nxt][i][0] = Asb[m * 36 + k];
                    afr[nxt][i][1] = Asb[(m + 8) * 36 + k];
                    afr[nxt][i][2] = Asb[m * 36 + k + 4];
                    afr[nxt][i][3] = Asb[(m + 8) * 36 + k + 4];
                }
                #pragma unroll
                for (int j = 0; j < 4; j++) {
                    const int n = warpN * 32 + j * 8 + grp;
                    bfr[nxt][j][0] = Bsb[n * 36 + k];
                    bfr[nxt][j][1] = Bsb[n * 36 + k + 4];
                }
            }
            #pragma unroll
            for (int i = 0; i < 4; i++)
                #pragma unroll
                for (int j = 0; j < 4; j++)
                    mma_tf32(acc[i][j], afr[cur][i], bfr[cur][j]);
        }
    }

    #pragma unroll
    for (int i = 0; i < 4; i++) {
        const long m0 = rowBase + warpM * 64 + i * 16 + grp;
        #pragma unroll
        for (int j = 0; j < 4; j++) {
            const int coff = warpN * 32 + j * 8 + 2 * tg;
            const int col = n0 + coff;
            #pragma unroll
            for (int rr = 0; rr < 2; rr++) {
                const long row = m0 + rr * 8;
                float v0 = acc[i][j][rr * 2 + 0] + bb[coff];
                float v1 = acc[i][j][rr * 2 + 1] + bb[coff + 1];
                if (g.act == 1) { v0 = gelu_exact(v0); v1 = gelu_exact(v1); }
                if (resid) {
                    const float* rp = resid + row * ldc + col;
                    v0 += rp[0]; v1 += rp[1];
                }
                *(float2*)(C + row * ldc + col) = make_float2(v0, v1);
            }
        }
    }
}

// ---------- tensor-core flash attention: 64 Q-rows/CTA, 64-col KV tiles ----------
struct AArgs {
    const float* Q[2]; const float* K[2]; const float* V[2];
    float* O[2];
    int ldq[2], ldk[2], ldv[2], ldo[2], causal[2];
};
#define AT_LD  104
#define AT_LDP 72
#define ATT_SMEM ((3*64*AT_LD + 64*AT_LDP) * 4)
__global__ __launch_bounds__(128)
void attn_tc(AArgs ar) {
    extern __shared__ uint32_t asm_[];
    uint32_t* Qs = asm_;
    uint32_t* Ks = asm_ + 64 * AT_LD;
    uint32_t* Vs = asm_ + 2 * 64 * AT_LD;
    uint32_t* Ps = asm_ + 3 * 64 * AT_LD;

    const int tid  = threadIdx.x;
    const int lane = tid & 31;
    const int w    = tid >> 5;
    const int grp  = lane >> 2;
    const int tg   = lane & 3;
    const int which = blockIdx.x >> 3;
    const int qt = blockIdx.x & 7;
    const int h  = blockIdx.y;
    const int b  = blockIdx.z;
    const float scale = 0.1020620726159658f;   // 1/sqrt(96)

    const int ldq = ar.ldq[which], ldk = ar.ldk[which], ldv = ar.ldv[which], ldo = ar.ldo[which];
    const int causal = ar.causal[which];
    const float* Qb = ar.Q[which] + ((long)b * Tc + qt * 64) * ldq + h * HDc;
    const float* Kb = ar.K[which] + (long)b * Tc * ldk + h * HDc;
    const float* Vb = ar.V[which] + (long)b * Tc * ldv + h * HDc;

    for (int i = tid; i < 64 * 24; i += 128) {
        int r = i / 24, c = (i % 24) * 4;
        *(uint4*)&Qs[r * AT_LD + c] = *(const uint4*)(Qb + (long)r * ldq + c);
    }

    float m_lo = -1e30f, m_hi = -1e30f, l_lo = 0.f, l_hi = 0.f;
    float oacc[12][4];
    #pragma unroll
    for (int d = 0; d < 12; d++)
        #pragma unroll
        for (int r = 0; r < 4; r++) oacc[d][r] = 0.f;

    const int m0 = w * 16 + grp;
    const int rowg_lo = qt * 64 + m0;
    const int rowg_hi = rowg_lo + 8;

    const int ktmax = causal ? qt : (Tc / 64 - 1);
    for (int kt = 0; kt <= ktmax; kt++) {
        __syncthreads();
        for (int i = tid; i < 64 * 24; i += 128) {
            int r = i / 24, c = (i % 24) * 4;
            *(uint4*)&Ks[r * AT_LD + c] = *(const uint4*)(Kb + (long)(kt * 64 + r) * ldk + c);
            *(uint4*)&Vs[r * AT_LD + c] = *(const uint4*)(Vb + (long)(kt * 64 + r) * ldv + c);
        }
        __syncthreads();

        float sacc[8][4];
        #pragma unroll
        for (int j = 0; j < 8; j++)
            #pragma unroll
            for (int r = 0; r < 4; r++) sacc[j][r] = 0.f;

        #pragma unroll
        for (int kk = 0; kk < 12; kk++) {
            const int k = kk * 8 + tg;
            uint32_t a[4];
            a[0] = Qs[m0 * AT_LD + k];
            a[1] = Qs[(m0 + 8) * AT_LD + k];
            a[2] = Qs[m0 * AT_LD + k + 4];
            a[3] = Qs[(m0 + 8) * AT_LD + k + 4];
            #pragma unroll
            for (int j = 0; j < 8; j++) {
                uint32_t bf[2];
                const int n = j * 8 + grp;
                bf[0] = Ks[n * AT_LD + k];
                bf[1] = Ks[n * AT_LD + k + 4];
                mma_tf32(sacc[j], a, bf);
            }
        }

        const bool dmask = causal && (kt == qt);
        float mt_lo = -1e30f, mt_hi = -1e30f;
        #pragma unroll
        for (int j = 0; j < 8; j++) {
            const int c = kt * 64 + j * 8 + 2 * tg;
            float s0 = sacc[j][0] * scale;
            float s1 = sacc[j][1] * scale;
            float s2 = sacc[j][2] * scale;
            float s3 = sacc[j][3] * scale;
            if (dmask) {
                if (c     > rowg_lo) s0 = -1e30f;
                if (c + 1 > rowg_lo) s1 = -1e30f;
                if (c     > rowg_hi) s2 = -1e30f;
                if (c + 1 > rowg_hi) s3 = -1e30f;
            }
            sacc[j][0] = s0; sacc[j][1] = s1; sacc[j][2] = s2; sacc[j][3] = s3;
            mt_lo = fmaxf(mt_lo, fmaxf(s0, s1));
            mt_hi = fmaxf(mt_hi, fmaxf(s2, s3));
        }
        mt_lo = fmaxf(mt_lo, __shfl_xor_sync(0xffffffffu, mt_lo, 1));
        mt_lo = fmaxf(mt_lo, __shfl_xor_sync(0xffffffffu, mt_lo, 2));
        mt_hi = fmaxf(mt_hi, __shfl_xor_sync(0xffffffffu, mt_hi, 1));
        mt_hi = fmaxf(mt_hi, __shfl_xor_sync(0xffffffffu, mt_hi, 2));

        const float mn_lo = fmaxf(m_lo, mt_lo);
        const float mn_hi = fmaxf(m_hi, mt_hi);
        const float al_lo = __expf(m_lo - mn_lo);
        const float al_hi = __expf(m_hi - mn_hi);

        float ps_lo = 0.f, ps_hi = 0.f;
        #pragma unroll
        for (int j = 0; j < 8; j++) {
            const int c = j * 8 + 2 * tg;
            float p0 = __expf(sacc[j][0] - mn_lo);
            float p1 = __expf(sacc[j][1] - mn_lo);
            float p2 = __expf(sacc[j][2] - mn_hi);
            float p3 = __expf(sacc[j][3] - mn_hi);
            ps_lo += p0 + p1;
            ps_hi += p2 + p3;
            Ps[m0 * AT_LDP + c]           = __float_as_uint(p0);
            Ps[m0 * AT_LDP + c + 1]       = __float_as_uint(p1);
            Ps[(m0 + 8) * AT_LDP + c]     = __float_as_uint(p2);
            Ps[(m0 + 8) * AT_LDP + c + 1] = __float_as_uint(p3);
        }
        ps_lo += __shfl_xor_sync(0xffffffffu, ps_lo, 1);
        ps_lo += __shfl_xor_sync(0xffffffffu, ps_lo, 2);
        ps_hi += __shfl_xor_sync(0xffffffffu, ps_hi, 1);
        ps_hi += __shfl_xor_sync(0xffffffffu, ps_hi, 2);

        l_lo = l_lo * al_lo + ps_lo;  m_lo = mn_lo;
        l_hi = l_hi * al_hi + ps_hi;  m_hi = mn_hi;
        #pragma unroll
        for (int d = 0; d < 12; d++) {
            oacc[d][0] *= al_lo; oacc[d][1] *= al_lo;
            oacc[d][2] *= al_hi; oacc[d][3] *= al_hi;
        }
        __syncwarp();

        #pragma unroll
        for (int kc = 0; kc < 8; kc++) {
            const int k = kc * 8 + tg;
            uint32_t a[4];
            a[0] = Ps[m0 * AT_LDP + k];
            a[1] = Ps[(m0 + 8) * AT_LDP + k];
            a[2] = Ps[m0 * AT_LDP + k + 4];
            a[3] = Ps[(m0 + 8) * AT_LDP + k + 4];
            #pragma unroll
            for (int d = 0; d < 12; d++) {
                uint32_t bf[2];
                const int n = d * 8 + grp;
                bf[0] = Vs[k * AT_LD + n];
                bf[1] = Vs[(k + 4) * AT_LD + n];
                mma_tf32(oacc[d], a, bf);
            }
        }
    }

    const float inv_lo = 1.0f / l_lo;
    const float inv_hi = 1.0f / l_hi;
    float* Ob = ar.O[which] + ((long)b * Tc + qt * 64 + w * 16) * ldo + h * HDc;
    #pragma unroll
    for (int d = 0; d < 12; d++) {
        const int c = d * 8 + 2 * tg;
        *(float2*)(Ob + (long)grp * ldo + c) =
            make_float2(oacc[d][0] * inv_lo, oacc[d][1] * inv_lo);
        *(float2*)(Ob + (long)(grp + 8) * ldo + c) =
            make_float2(oacc[d][2] * inv_hi, oacc[d][3] * inv_hi);
    }
}

// ---------------- host driver ----------------
static GArgs mkargs() {
    GArgs g;
    for (int i = 0; i < 4; i++) {
        g.A[i]=0; g.W[i]=0; g.bias[i]=0; g.resid[i]=0; g.C[i]=0;
        g.ldc[i]=0; g.lda[i]=0; g.wstride[i]=0; g.eidx[i]=0; g.yOff[i]=0;
    }
    g.nSlices=1; g.ldw=0; g.bstride=0; g.Kdim=0; g.act=0;
    return g;
}

extern "C" void kernel_launch(void* const* d_in, const int* in_sizes, int n_in,
                              void* d_out, int out_size) {
    (void)in_sizes; (void)n_in; (void)out_size;
    const float* x       = (const float*)d_in[0];
    const float* r_w1    = (const float*)d_in[1];
    const float* r_b1    = (const float*)d_in[2];
    const float* r_w2    = (const float*)d_in[3];
    const float* r_b2    = (const float*)d_in[4];
    const float* ns_g    = (const float*)d_in[5];
    const float* ns_b    = (const float*)d_in[6];
    const float* nt_g    = (const float*)d_in[7];
    const float* nt_b    = (const float*)d_in[8];
    const float* nm_g    = (const float*)d_in[9];
    const float* nm_b    = (const float*)d_in[10];
    const float* sp_wqkv = (const float*)d_in[11];
    const float* sp_bqkv = (const float*)d_in[12];
    const float* sp_wo   = (const float*)d_in[13];
    const float* sp_bo   = (const float*)d_in[14];
    const float* tp_wq   = (const float*)d_in[15];
    const float* tp_bq   = (const float*)d_in[16];
    const float* tp_wk   = (const float*)d_in[17];
    const float* tp_bk   = (const float*)d_in[18];
    const float* tp_wv   = (const float*)d_in[19];
    const float* tp_bv   = (const float*)d_in[20];
    const float* tp_wo   = (const float*)d_in[21];
    const float* tp_bo   = (const float*)d_in[22];
    const float* c_wqkv  = (const float*)d_in[23];
    const float* c_bqkv  = (const float*)d_in[24];
    const float* c_wo    = (const float*)d_in[25];
    const float* c_bo    = (const float*)d_in[26];
    const float* m_w1    = (const float*)d_in[27];
    const float* m_b1    = (const float*)d_in[28];
    const float* m_w2    = (const float*)d_in[29];
    const float* m_b2    = (const float*)d_in[30];
    float* out = (float*)d_out;

    float *mean, *xns, *xt, *qkv, *qt, *kt, *vt, *att, *att2, *spat, *temp, *cq, *ckv, *x1, *xm, *y;
    int *idx_s, *idx_t;
    cudaGetSymbolAddress((void**)&mean,  g_mean);
    cudaGetSymbolAddress((void**)&idx_s, g_idx_s);
    cudaGetSymbolAddress((void**)&idx_t, g_idx_t);
    cudaGetSymbolAddress((void**)&xns,   g_xns);
    cudaGetSymbolAddress((void**)&xt,    g_xt);
    cudaGetSymbolAddress((void**)&qkv,   g_qkv);
    cudaGetSymbolAddress((void**)&qt,    g_qt);
    cudaGetSymbolAddress((void**)&kt,    g_kt);
    cudaGetSymbolAddress((void**)&vt,    g_vt);
    cudaGetSymbolAddress((void**)&att,   g_att);
    cudaGetSymbolAddress((void**)&att2,  g_att2);
    cudaGetSymbolAddress((void**)&spat,  g_spat);
    cudaGetSymbolAddress((void**)&temp,  g_temp);
    cudaGetSymbolAddress((void**)&cq,    g_cq);
    cudaGetSymbolAddress((void**)&ckv,   g_ckv);
    cudaGetSymbolAddress((void**)&x1,    g_x1);
    cudaGetSymbolAddress((void**)&xm,    g_xm);
    cudaGetSymbolAddress((void**)&y,     g_y);

    cudaFuncSetAttribute(gemm_tc, cudaFuncAttributeMaxDynamicSharedMemorySize, GEMM_SMEM);
    cudaFuncSetAttribute(attn_tc, cudaFuncAttributeMaxDynamicSharedMemorySize, ATT_SMEM);

    rmean_kernel<<<Bc, Dc>>>(x, mean);
    router_kernel<<<Bc, 128>>>(mean, r_w1, r_b1, r_w2, r_b2, idx_s, idx_t);

    ln2_kernel<<<dim3(BTc, 2), 256>>>(x, ns_g, ns_b, xns, nt_g, nt_b, xt);

    // ---- spatial qkv + temporal q/k/v fused (4 slices, 36 y-blocks) ----
    {
        GArgs a = mkargs();
        a.A[0] = xns; a.W[0] = sp_wqkv; a.bias[0] = sp_bqkv; a.C[0] = qkv; a.ldc[0] = 3 * Dc;
        a.wstride[0] = (long)3 * Dc * Dc; a.eidx[0] = idx_s; a.lda[0] = Dc; a.yOff[0] = 0;
        a.A[1] = xt; a.W[1] = tp_wq; a.bias[1] = tp_bq; a.C[1] = qt; a.ldc[1] = Dc;
        a.wstride[1] = (long)Dc * Dc; a.eidx[1] = idx_t; a.lda[1] = Dc; a.yOff[1] = 18;
        a.A[2] = xt; a.W[2] = tp_wk; a.bias[2] = tp_bk; a.C[2] = kt; a.ldc[2] = Dc;
        a.wstride[2] = (long)Dc * Dc; a.eidx[2] = idx_t; a.lda[2] = Dc; a.yOff[2] = 24;
        a.A[3] = xt; a.W[3] = tp_wv; a.bias[3] = tp_bv; a.C[3] = vt; a.ldc[3] = Dc;
        a.wstride[3] = (long)Dc * Dc; a.eidx[3] = idx_t; a.lda[3] = Dc; a.yOff[3] = 30;
        a.nSlices = 4; a.ldw = Dc;
        a.bstride = -1;   // bias stride = ldc[slice] (3*Dc spatial, Dc temporal)
        a.Kdim = Dc; a.act = 0;
        gemm_tc<<<dim3(4, 36, 8), 256, GEMM_SMEM>>>(a);
    }

    // ---- both flash attentions in one launch ----
    {
        AArgs ar;
        ar.Q[0] = qkv;      ar.K[0] = qkv + Dc; ar.V[0] = qkv + 2 * Dc; ar.O[0] = att;
        ar.ldq[0] = 3 * Dc; ar.ldk[0] = 3 * Dc; ar.ldv[0] = 3 * Dc;     ar.ldo[0] = Dc; ar.causal[0] = 0;
        ar.Q[1] = qt;       ar.K[1] = kt;       ar.V[1] = vt;           ar.O[1] = att2;
        ar.ldq[1] = Dc;     ar.ldk[1] = Dc;     ar.ldv[1] = Dc;         ar.ldo[1] = Dc; ar.causal[1] = 1;
        attn_tc<<<dim3(16, 8, 8), 128, ATT_SMEM>>>(ar);
    }

    // ---- both Wo projections in one launch ----
    {
        GArgs a = mkargs();
        a.A[0] = att;  a.W[0] = sp_wo; a.bias[0] = sp_bo; a.C[0] = spat; a.ldc[0] = Dc;
        a.wstride[0] = (long)Dc * Dc; a.eidx[0] = idx_s; a.lda[0] = Dc; a.yOff[0] = 0;
        a.A[1] = att2; a.W[1] = tp_wo; a.bias[1] = tp_bo; a.C[1] = temp; a.ldc[1] = Dc;
        a.wstride[1] = (long)Dc * Dc; a.eidx[1] = idx_t; a.lda[1] = Dc; a.yOff[1] = 6;
        a.resid[1] = xt;
        a.nSlices = 2; a.ldw = Dc; a.bstride = Dc; a.Kdim = Dc; a.act = 0;
        gemm_tc<<<dim3(4, 12, 8), 256, GEMM_SMEM>>>(a);
    }

    // ---- cross qkv fused ----
    {
        GArgs a = mkargs();
        a.A[0] = spat; a.W[0] = c_wqkv;               a.bias[0] = c_bqkv;          a.C[0] = cq;       a.ldc[0] = Dc;     a.lda[0] = Dc; a.yOff[0] = 0;
        a.A[1] = temp; a.W[1] = c_wqkv + Dc * Dc;     a.bias[1] = c_bqkv + Dc;     a.C[1] = ckv;      a.ldc[1] = 2 * Dc; a.lda[1] = Dc; a.yOff[1] = 6;
        a.A[2] = temp; a.W[2] = c_wqkv + 2 * Dc * Dc; a.bias[2] = c_bqkv + 2 * Dc; a.C[2] = ckv + Dc; a.ldc[2] = 2 * Dc; a.lda[2] = Dc; a.yOff[2] = 12;
        a.nSlices = 3; a.ldw = Dc; a.bstride = 0; a.Kdim = Dc; a.act = 0;
        gemm_tc<<<dim3(32, 18, 1), 256, GEMM_SMEM>>>(a);
    }
    {
        AArgs ar;
        ar.Q[0] = cq;   ar.K[0] = ckv;      ar.V[0] = ckv + Dc;  ar.O[0] = att;
        ar.ldq[0] = Dc; ar.ldk[0] = 2 * Dc; ar.ldv[0] = 2 * Dc;  ar.ldo[0] = Dc; ar.causal[0] = 0;
        ar.Q[1] = cq;   ar.K[1] = ckv;      ar.V[1] = ckv + Dc;  ar.O[1] = att;
        ar.ldq[1] = Dc; ar.ldk[1] = 2 * Dc; ar.ldv[1] = 2 * Dc;  ar.ldo[1] = Dc; ar.causal[1] = 0;
        attn_tc<<<dim3(8, 8, 8), 128, ATT_SMEM>>>(ar);
    }
    {
        GArgs a = mkargs();
        a.A[0] = att; a.W[0] = c_wo; a.bias[0] = c_bo; a.C[0] = x1; a.ldc[0] = Dc;
        a.lda[0] = Dc; a.resid[0] = x;
        a.nSlices = 1; a.ldw = Dc; a.bstride = 0; a.Kdim = Dc; a.act = 0;
        gemm_tc<<<dim3(32, 6, 1), 256, GEMM_SMEM>>>(a);
    }

    // ---- MLP with residual ----
    ln_kernel<<<BTc, 256>>>(x1, nm_g, nm_b, xm);
    {
        GArgs a = mkargs();
        a.A[0] = xm; a.W[0] = m_w1; a.bias[0] = m_b1; a.C[0] = y; a.ldc[0] = 4 * Dc;
        a.lda[0] = Dc;
        a.nSlices = 1; a.ldw = Dc; a.bstride = 0; a.Kdim = Dc; a.act = 1;
        gemm_tc<<<dim3(32, 24, 1), 256, GEMM_SMEM>>>(a);
    }
    {
        GArgs a = mkargs();
        a.A[0] = y; a.W[0] = m_w2; a.bias[0] = m_b2; a.C[0] = out; a.ldc[0] = Dc;
        a.lda[0] = 4 * Dc; a.resid[0] = x1;
        a.nSlices = 1; a.ldw = 4 * Dc; a.bstride = 0; a.Kdim = 4 * Dc; a.act = 0;
        gemm_tc<<<dim3(32, 6, 1), 256, GEMM_SMEM>>>(a);
    }
}

// round 14
// speedup vs baseline: 1.4434x; 1.4409x over previous
#include <cuda_runtime.h>
#include <math.h>
#include <stdint.h>

// Problem constants
#define Bc 8
#define Tc 512
#define Dc 768
#define Hc 8
#define HDc 96
#define BTc (Bc*Tc)

// ---------------- scratch (device globals; no cudaMalloc allowed) ----------------
__device__ __align__(16) float g_mean[Bc*Dc];
__device__ int   g_idx_s[Bc];
__device__ int   g_idx_t[Bc];
__device__ __align__(16) float g_xns [BTc*Dc];
__device__ __align__(16) float g_xt  [BTc*Dc];
__device__ __align__(16) float g_qkv [BTc*3*Dc];
__device__ __align__(16) float g_qt  [BTc*Dc];
__device__ __align__(16) float g_kt  [BTc*Dc];
__device__ __align__(16) float g_vt  [BTc*Dc];
__device__ __align__(16) float g_att [BTc*Dc];
__device__ __align__(16) float g_att2[BTc*Dc];
__device__ __align__(16) float g_spat[BTc*Dc];
__device__ __align__(16) float g_temp[BTc*Dc];
__device__ __align__(16) float g_cq  [BTc*Dc];
__device__ __align__(16) float g_ckv [BTc*2*Dc];
__device__ __align__(16) float g_x1  [BTc*Dc];
__device__ __align__(16) float g_xm  [BTc*Dc];
__device__ __align__(16) float g_y   [BTc*4*Dc];

__device__ __forceinline__ float gelu_exact(float v) {
    return 0.5f * v * (1.0f + erff(v * 0.70710678118654752f));
}

__device__ __forceinline__ void mma_tf32(float* c, const uint32_t* a, const uint32_t* b) {
    asm volatile(
        "mma.sync.aligned.m16n8k8.row.col.f32.tf32.tf32.f32 "
        "{%0,%1,%2,%3}, {%4,%5,%6,%7}, {%8,%9}, {%0,%1,%2,%3};\n"
        : "+f"(c[0]), "+f"(c[1]), "+f"(c[2]), "+f"(c[3])
        : "r"(a[0]), "r"(a[1]), "r"(a[2]), "r"(a[3]),
          "r"(b[0]), "r"(b[1]));
}

__device__ __forceinline__ void cp16(uint32_t saddr, const void* g) {
    asm volatile("cp.async.cg.shared.global [%0], [%1], 16;" :: "r"(saddr), "l"(g));
}
#define CP_COMMIT() asm volatile("cp.async.commit_group;" ::: "memory")
#define CP_WAIT0()  asm volatile("cp.async.wait_group 0;" ::: "memory")

// ---------------- router part 1: mean over T ----------------
__global__ void rmean_kernel(const float* __restrict__ x, float* __restrict__ mean) {
    int b = blockIdx.x;
    int d = threadIdx.x;            // 768 threads
    float s = 0.f;
    const float* xb = x + (long)b * Tc * Dc + d;
    #pragma unroll 8
    for (int t = 0; t < Tc; t++) s += xb[(long)t * Dc];
    mean[b * Dc + d] = s * (1.0f / (float)Tc);
}

// ---------------- router part 2: MLP -> argmax experts ----------------
__global__ void router_kernel(const float* __restrict__ mean,
                              const float* __restrict__ w1, const float* __restrict__ b1,
                              const float* __restrict__ w2, const float* __restrict__ b2,
                              int* __restrict__ idx_s, int* __restrict__ idx_t) {
    int b = blockIdx.x;
    int j = threadIdx.x;            // 128 threads
    __shared__ float h[128];
    __shared__ float lg[8];
    float a = b1[j];
    const float* mb = mean + b * Dc;
    const float* wr = w1 + j * Dc;
    for (int d = 0; d < Dc; d++) a += mb[d] * wr[d];
    h[j] = gelu_exact(a);
    __syncthreads();
    if (j < 8) {
        float a2 = b2[j];
        const float* wrr = w2 + j * 128;
        for (int i = 0; i < 128; i++) a2 += h[i] * wrr[i];
        lg[j] = a2;
    }
    __syncthreads();
    if (j == 0) {
        int bi = 0;
        for (int i = 1; i < 4; i++) if (lg[i] > lg[bi]) bi = i;
        idx_s[b] = bi;
        int bt = 4;
        for (int i = 5; i < 8; i++) if (lg[i] > lg[bt]) bt = i;
        idx_t[b] = bt - 4;
    }
}

// ---------------- LayerNorm over D=768, one row per block, 2 param sets ------
__global__ __launch_bounds__(256)
void ln2_kernel(const float* __restrict__ x,
                const float* __restrict__ g0, const float* __restrict__ b0,
                float* __restrict__ o0,
                const float* __restrict__ g1, const float* __restrict__ b1,
                float* __restrict__ o1) {
    long row = blockIdx.x;
    const float* g   = blockIdx.y ? g1 : g0;
    const float* bet = blockIdx.y ? b1 : b0;
    float* o         = blockIdx.y ? o1 : o0;
    int tid = threadIdx.x;
    const float* xr = x + row * Dc;
    float v0 = xr[tid], v1 = xr[tid + 256], v2 = xr[tid + 512];
    float s  = v0 + v1 + v2;
    float ss = v0 * v0 + v1 * v1 + v2 * v2;
    #pragma unroll
    for (int off = 16; off > 0; off >>= 1) {
        s  += __shfl_xor_sync(0xffffffffu, s,  off);
        ss += __shfl_xor_sync(0xffffffffu, ss, off);
    }
    __shared__ float rs[8], rss[8];
    int lane = tid & 31, wid = tid >> 5;
    if (lane == 0) { rs[wid] = s; rss[wid] = ss; }
    __syncthreads();
    if (tid == 0) {
        float S = 0.f, SS = 0.f;
        for (int i = 0; i < 8; i++) { S += rs[i]; SS += rss[i]; }
        float mean = S * (1.0f / (float)Dc);
        float var  = SS * (1.0f / (float)Dc) - mean * mean;
        rs[0] = mean;
        rss[0] = rsqrtf(var + 1e-5f);
    }
    __syncthreads();
    float mean = rs[0], inv = rss[0];
    float* orow = o + row * Dc;
    orow[tid]       = (v0 - mean) * inv * g[tid]       + bet[tid];
    orow[tid + 256] = (v1 - mean) * inv * g[tid + 256] + bet[tid + 256];
    orow[tid + 512] = (v2 - mean) * inv * g[tid + 512] + bet[tid + 512];
}

__global__ __launch_bounds__(256)
void ln_kernel(const float* __restrict__ x, const float* __restrict__ g,
               const float* __restrict__ bet, float* __restrict__ o) {
    long row = blockIdx.x;
    int tid = threadIdx.x;
    const float* xr = x + row * Dc;
    float v0 = xr[tid], v1 = xr[tid + 256], v2 = xr[tid + 512];
    float s  = v0 + v1 + v2;
    float ss = v0 * v0 + v1 * v1 + v2 * v2;
    #pragma unroll
    for (int off = 16; off > 0; off >>= 1) {
        s  += __shfl_xor_sync(0xffffffffu, s,  off);
        ss += __shfl_xor_sync(0xffffffffu, ss, off);
    }
    __shared__ float rs[8], rss[8];
    int lane = tid & 31, wid = tid >> 5;
    if (lane == 0) { rs[wid] = s; rss[wid] = ss; }
    __syncthreads();
    if (tid == 0) {
        float S = 0.f, SS = 0.f;
        for (int i = 0; i < 8; i++) { S += rs[i]; SS += rss[i]; }
        float mean = S * (1.0f / (float)Dc);
        float var  = SS * (1.0f / (float)Dc) - mean * mean;
        rs[0] = mean;
        rss[0] = rsqrtf(var + 1e-5f);
    }
    __syncthreads();
    float mean = rs[0], inv = rss[0];
    float* orow = o + row * Dc;
    orow[tid]       = (v0 - mean) * inv * g[tid]       + bet[tid];
    orow[tid + 256] = (v1 - mean) * inv * g[tid + 256] + bet[tid + 256];
    orow[tid + 512] = (v2 - mean) * inv * g[tid + 512] + bet[tid + 512];
}

// ------------- tensor-core GEMM: C = act(A @ W^T + bias) [+ resid] ------------
// TF32 mma.sync m16n8k8, fp32 accumulate, raw-fp32-bit operands.
// Tiles 128(M) x 64(N) x 32(K), 2-stage cp.async pipeline (54 KB smem),
// 256 threads = 8 warps in 4(M) x 2(N), warp tile 32x32.
// __launch_bounds__(256,3): 3 CTAs/SM (occupancy-directed; latency-bound loop).
struct GArgs {
    const float* A[4];
    const float* W[4];
    const float* bias[4];
    const float* resid[4];
    float* C[4];
    int ldc[4];
    int lda[4];
    long wstride[4];
    const int* eidx[4];
    int yOff[4];
    int nSlices;
    int ldw, bstride;      // bstride < 0 => use ldc[slice] as bias stride
    int Kdim, act;
};

#define GROWS 192                         // 128 A rows + 64 B rows
#define GSTAGE_U32 (GROWS * 36)
#define GEMM_SMEM  (2 * GSTAGE_U32 * 4)   // 55296 B

__global__ __launch_bounds__(256, 3)
void gemm_tc(GArgs g) {
    extern __shared__ uint32_t sm[];
    const uint32_t sb = (uint32_t)__cvta_generic_to_shared(sm);

    const int tid  = threadIdx.x;
    const int wid  = tid >> 5;
    const int lane = tid & 31;
    const int grp  = lane >> 2;        // 0..7
    const int tg   = lane & 3;         // 0..3
    const int warpM = wid & 3;         // 0..3  (32 rows each)
    const int warpN = wid >> 2;        // 0..1  (32 cols each)

    const int y = blockIdx.y;
    int slice = 0;
    #pragma unroll
    for (int i = 1; i < 4; i++)
        if (i < g.nSlices && y >= g.yOff[i]) slice = i;
    const int n0 = (y - g.yOff[slice]) * 64;

    const int bz = blockIdx.z;
    const long rowBase = ((long)bz * gridDim.x + blockIdx.x) * 128;

    const int lda = g.lda[slice];
    const int ldc = g.ldc[slice];
    const int bstr = (g.bstride < 0) ? ldc : g.bstride;
    const int e = g.eidx[slice] ? g.eidx[slice][bz] : 0;
    const float* Ab = g.A[slice] + rowBase * lda;
    const float* Wb = g.W[slice] + (long)e * g.wstride[slice] + (long)n0 * g.ldw;
    const float* bb = g.bias[slice] + (long)e * bstr + n0;
    const float* resid = g.resid[slice];
    float* C = g.C[slice];

    float acc[2][4][4];
    #pragma unroll
    for (int i = 0; i < 2; i++)
        #pragma unroll
        for (int j = 0; j < 4; j++)
            #pragma unroll
            for (int r = 0; r < 4; r++) acc[i][j][r] = 0.f;

    // tile loader mapping: 192 rows x 32 floats = 1536 float4 chunks; 6/thread.
    // warp-uniform A/B split (row boundary 128 aligns with chunk 1024 = q=4,tid=0).
    const int ldw_ = g.ldw;
    const int nK = g.Kdim >> 5;

    // prologue: stage 0 <- tile 0
    {
        const uint32_t base = sb;
        #pragma unroll
        for (int q = 0; q < 6; q++) {
            const int idx = q * 256 + tid;
            const int row = idx >> 3;
            const int c = (idx & 7) * 4;
            const float* gp = (row < 128)
                ? (Ab + (long)row * lda + c)
                : (Wb + (long)(row - 128) * ldw_ + c);
            cp16(base + (row * 36 + c) * 4, gp);
        }
        CP_COMMIT();
    }

    for (int kt = 0; kt < nK; kt++) {
        CP_WAIT0();
        __syncthreads();

        if (kt + 1 < nK) {
            const uint32_t base = sb + ((kt + 1) & 1) * (GSTAGE_U32 * 4);
            const int k0 = (kt + 1) * 32;
            #pragma unroll
            for (int q = 0; q < 6; q++) {
                const int idx = q * 256 + tid;
                const int row = idx >> 3;
                const int c = (idx & 7) * 4;
                const float* gp = (row < 128)
                    ? (Ab + (long)row * lda + k0 + c)
                    : (Wb + (long)(row - 128) * ldw_ + k0 + c);
                cp16(base + (row * 36 + c) * 4, gp);
            }
            CP_COMMIT();
        }

        const uint32_t* Asb = sm + (kt & 1) * GSTAGE_U32;
        const uint32_t* Bsb = Asb + 128 * 36;

        #pragma unroll
        for (int kk = 0; kk < 4; kk++) {
            const int k = kk * 8 + tg;
            uint32_t afr[2][4];
            #pragma unroll
            for (int i = 0; i < 2; i++) {
                const int m = warpM * 32 + i * 16 + grp;
                afr[i][0] = Asb[m * 36 + k];
                afr[i][1] = Asb[(m + 8) * 36 + k];
                afr[i][2] = Asb[m * 36 + k + 4];
                afr[i][3] = Asb[(m + 8) * 36 + k + 4];
            }
            uint32_t bfr[4][2];
            #pragma unroll
            for (int j = 0; j < 4; j++) {
                const int n = warpN * 32 + j * 8 + grp;
                bfr[j][0] = Bsb[n * 36 + k];
                bfr[j][1] = Bsb[n * 36 + k + 4];
            }
            #pragma unroll
            for (int i = 0; i < 2; i++)
                #pragma unroll
                for (int j = 0; j < 4; j++)
                    mma_tf32(acc[i][j], afr[i], bfr[j]);
        }
    }

    #pragma unroll
    for (int i = 0; i < 2; i++) {
        const long m0 = rowBase + warpM * 32 + i * 16 + grp;
        #pragma unroll
        for (int j = 0; j < 4; j++) {
            const int coff = warpN * 32 + j * 8 + 2 * tg;
            const int col = n0 + coff;
            #pragma unroll
            for (int rr = 0; rr < 2; rr++) {
                const long row = m0 + rr * 8;
                float v0 = acc[i][j][rr * 2 + 0] + bb[coff];
                float v1 = acc[i][j][rr * 2 + 1] + bb[coff + 1];
                if (g.act == 1) { v0 = gelu_exact(v0); v1 = gelu_exact(v1); }
                if (resid) {
                    const float* rp = resid + row * ldc + col;
                    v0 += rp[0]; v1 += rp[1];
                }
                *(float2*)(C + row * ldc + col) = make_float2(v0, v1);
            }
        }
    }
}

// ---------- tensor-core flash attention: 64 Q-rows/CTA, 64-col KV tiles ----------
// 128 threads = 4 warps; warp w owns Q rows [16w, 16w+16) -> softmax warp-local.
#define AT_LD  104
#define AT_LDP 72
#define ATT_SMEM ((3*64*AT_LD + 64*AT_LDP) * 4)
__global__ __launch_bounds__(128)
void attn_tc(const float* __restrict__ Qp, int ldq,
             const float* __restrict__ Kp, int ldk,
             const float* __restrict__ Vp, int ldv,
             float* __restrict__ Op, int ldo, int causal) {
    extern __shared__ uint32_t asm_[];
    uint32_t* Qs = asm_;
    uint32_t* Ks = asm_ + 64 * AT_LD;
    uint32_t* Vs = asm_ + 2 * 64 * AT_LD;
    uint32_t* Ps = asm_ + 3 * 64 * AT_LD;

    const int tid  = threadIdx.x;
    const int lane = tid & 31;
    const int w    = tid >> 5;
    const int grp  = lane >> 2;
    const int tg   = lane & 3;
    const int qt = blockIdx.x;
    const int h  = blockIdx.y;
    const int b  = blockIdx.z;
    const float scale = 0.1020620726159658f;   // 1/sqrt(96)

    const float* Qb = Qp + ((long)b * Tc + qt * 64) * ldq + h * HDc;
    const float* Kb = Kp + (long)b * Tc * ldk + h * HDc;
    const float* Vb = Vp + (long)b * Tc * ldv + h * HDc;

    for (int i = tid; i < 64 * 24; i += 128) {
        int r = i / 24, c = (i % 24) * 4;
        *(uint4*)&Qs[r * AT_LD + c] = *(const uint4*)(Qb + (long)r * ldq + c);
    }

    float m_lo = -1e30f, m_hi = -1e30f, l_lo = 0.f, l_hi = 0.f;
    float oacc[12][4];
    #pragma unroll
    for (int d = 0; d < 12; d++)
        #pragma unroll
        for (int r = 0; r < 4; r++) oacc[d][r] = 0.f;

    const int m0 = w * 16 + grp;
    const int rowg_lo = qt * 64 + m0;
    const int rowg_hi = rowg_lo + 8;

    const int ktmax = causal ? qt : (Tc / 64 - 1);
    for (int kt = 0; kt <= ktmax; kt++) {
        __syncthreads();
        for (int i = tid; i < 64 * 24; i += 128) {
            int r = i / 24, c = (i % 24) * 4;
            *(uint4*)&Ks[r * AT_LD + c] = *(const uint4*)(Kb + (long)(kt * 64 + r) * ldk + c);
            *(uint4*)&Vs[r * AT_LD + c] = *(const uint4*)(Vb + (long)(kt * 64 + r) * ldv + c);
        }
        __syncthreads();

        float sacc[8][4];
        #pragma unroll
        for (int j = 0; j < 8; j++)
            #pragma unroll
            for (int r = 0; r < 4; r++) sacc[j][r] = 0.f;

        #pragma unroll
        for (int kk = 0; kk < 12; kk++) {
            const int k = kk * 8 + tg;
            uint32_t a[4];
            a[0] = Qs[m0 * AT_LD + k];
            a[1] = Qs[(m0 + 8) * AT_LD + k];
            a[2] = Qs[m0 * AT_LD + k + 4];
            a[3] = Qs[(m0 + 8) * AT_LD + k + 4];
            #pragma unroll
            for (int j = 0; j < 8; j++) {
                uint32_t bf[2];
                const int n = j * 8 + grp;
                bf[0] = Ks[n * AT_LD + k];
                bf[1] = Ks[n * AT_LD + k + 4];
                mma_tf32(sacc[j], a, bf);
            }
        }

        const bool dmask = causal && (kt == qt);
        float mt_lo = -1e30f, mt_hi = -1e30f;
        #pragma unroll
        for (int j = 0; j < 8; j++) {
            const int c = kt * 64 + j * 8 + 2 * tg;
            float s0 = sacc[j][0] * scale;
            float s1 = sacc[j][1] * scale;
            float s2 = sacc[j][2] * scale;
            float s3 = sacc[j][3] * scale;
            if (dmask) {
                if (c     > rowg_lo) s0 = -1e30f;
                if (c + 1 > rowg_lo) s1 = -1e30f;
                if (c     > rowg_hi) s2 = -1e30f;
                if (c + 1 > rowg_hi) s3 = -1e30f;
            }
            sacc[j][0] = s0; sacc[j][1] = s1; sacc[j][2] = s2; sacc[j][3] = s3;
            mt_lo = fmaxf(mt_lo, fmaxf(s0, s1));
            mt_hi = fmaxf(mt_hi, fmaxf(s2, s3));
        }
        mt_lo = fmaxf(mt_lo, __shfl_xor_sync(0xffffffffu, mt_lo, 1));
        mt_lo = fmaxf(mt_lo, __shfl_xor_sync(0xffffffffu, mt_lo, 2));
        mt_hi = fmaxf(mt_hi, __shfl_xor_sync(0xffffffffu, mt_hi, 1));
        mt_hi = fmaxf(mt_hi, __shfl_xor_sync(0xffffffffu, mt_hi, 2));

        const float mn_lo = fmaxf(m_lo, mt_lo);
        const float mn_hi = fmaxf(m_hi, mt_hi);
        const float al_lo = __expf(m_lo - mn_lo);
        const float al_hi = __expf(m_hi - mn_hi);

        float ps_lo = 0.f, ps_hi = 0.f;
        #pragma unroll
        for (int j = 0; j < 8; j++) {
            const int c = j * 8 + 2 * tg;
            float p0 = __expf(sacc[j][0] - mn_lo);
            float p1 = __expf(sacc[j][1] - mn_lo);
            float p2 = __expf(sacc[j][2] - mn_hi);
            float p3 = __expf(sacc[j][3] - mn_hi);
            ps_lo += p0 + p1;
            ps_hi += p2 + p3;
            Ps[m0 * AT_LDP + c]           = __float_as_uint(p0);
            Ps[m0 * AT_LDP + c + 1]       = __float_as_uint(p1);
            Ps[(m0 + 8) * AT_LDP + c]     = __float_as_uint(p2);
            Ps[(m0 + 8) * AT_LDP + c + 1] = __float_as_uint(p3);
        }
        ps_lo += __shfl_xor_sync(0xffffffffu, ps_lo, 1);
        ps_lo += __shfl_xor_sync(0xffffffffu, ps_lo, 2);
        ps_hi += __shfl_xor_sync(0xffffffffu, ps_hi, 1);
        ps_hi += __shfl_xor_sync(0xffffffffu, ps_hi, 2);

        l_lo = l_lo * al_lo + ps_lo;  m_lo = mn_lo;
        l_hi = l_hi * al_hi + ps_hi;  m_hi = mn_hi;
        #pragma unroll
        for (int d = 0; d < 12; d++) {
            oacc[d][0] *= al_lo; oacc[d][1] *= al_lo;
            oacc[d][2] *= al_hi; oacc[d][3] *= al_hi;
        }
        __syncwarp();

        #pragma unroll
        for (int kc = 0; kc < 8; kc++) {
            const int k = kc * 8 + tg;
            uint32_t a[4];
            a[0] = Ps[m0 * AT_LDP + k];
            a[1] = Ps[(m0 + 8) * AT_LDP + k];
            a[2] = Ps[m0 * AT_LDP + k + 4];
            a[3] = Ps[(m0 + 8) * AT_LDP + k + 4];
            #pragma unroll
            for (int d = 0; d < 12; d++) {
                uint32_t bf[2];
                const int n = d * 8 + grp;
                bf[0] = Vs[k * AT_LD + n];
                bf[1] = Vs[(k + 4) * AT_LD + n];
                mma_tf32(oacc[d], a, bf);
            }
        }
    }

    const float inv_lo = 1.0f / l_lo;
    const float inv_hi = 1.0f / l_hi;
    float* Ob = Op + ((long)b * Tc + qt * 64 + w * 16) * ldo + h * HDc;
    #pragma unroll
    for (int d = 0; d < 12; d++) {
        const int c = d * 8 + 2 * tg;
        *(float2*)(Ob + (long)grp * ldo + c) =
            make_float2(oacc[d][0] * inv_lo, oacc[d][1] * inv_lo);
        *(float2*)(Ob + (long)(grp + 8) * ldo + c) =
            make_float2(oacc[d][2] * inv_hi, oacc[d][3] * inv_hi);
    }
}

// ---------------- host driver ----------------
static GArgs mkargs() {
    GArgs g;
    for (int i = 0; i < 4; i++) {
        g.A[i]=0; g.W[i]=0; g.bias[i]=0; g.resid[i]=0; g.C[i]=0;
        g.ldc[i]=0; g.lda[i]=0; g.wstride[i]=0; g.eidx[i]=0; g.yOff[i]=0;
    }
    g.nSlices=1; g.ldw=0; g.bstride=0; g.Kdim=0; g.act=0;
    return g;
}

extern "C" void kernel_launch(void* const* d_in, const int* in_sizes, int n_in,
                              void* d_out, int out_size) {
    (void)in_sizes; (void)n_in; (void)out_size;
    const float* x       = (const float*)d_in[0];
    const float* r_w1    = (const float*)d_in[1];
    const float* r_b1    = (const float*)d_in[2];
    const float* r_w2    = (const float*)d_in[3];
    const float* r_b2    = (const float*)d_in[4];
    const float* ns_g    = (const float*)d_in[5];
    const float* ns_b    = (const float*)d_in[6];
    const float* nt_g    = (const float*)d_in[7];
    const float* nt_b    = (const float*)d_in[8];
    const float* nm_g    = (const float*)d_in[9];
    const float* nm_b    = (const float*)d_in[10];
    const float* sp_wqkv = (const float*)d_in[11];
    const float* sp_bqkv = (const float*)d_in[12];
    const float* sp_wo   = (const float*)d_in[13];
    const float* sp_bo   = (const float*)d_in[14];
    const float* tp_wq   = (const float*)d_in[15];
    const float* tp_bq   = (const float*)d_in[16];
    const float* tp_wk   = (const float*)d_in[17];
    const float* tp_bk   = (const float*)d_in[18];
    const float* tp_wv   = (const float*)d_in[19];
    const float* tp_bv   = (const float*)d_in[20];
    const float* tp_wo   = (const float*)d_in[21];
    const float* tp_bo   = (const float*)d_in[22];
    const float* c_wqkv  = (const float*)d_in[23];
    const float* c_bqkv  = (const float*)d_in[24];
    const float* c_wo    = (const float*)d_in[25];
    const float* c_bo    = (const float*)d_in[26];
    const float* m_w1    = (const float*)d_in[27];
    const float* m_b1    = (const float*)d_in[28];
    const float* m_w2    = (const float*)d_in[29];
    const float* m_b2    = (const float*)d_in[30];
    float* out = (float*)d_out;

    float *mean, *xns, *xt, *qkv, *qt, *kt, *vt, *att, *att2, *spat, *temp, *cq, *ckv, *x1, *xm, *y;
    int *idx_s, *idx_t;
    cudaGetSymbolAddress((void**)&mean,  g_mean);
    cudaGetSymbolAddress((void**)&idx_s, g_idx_s);
    cudaGetSymbolAddress((void**)&idx_t, g_idx_t);
    cudaGetSymbolAddress((void**)&xns,   g_xns);
    cudaGetSymbolAddress((void**)&xt,    g_xt);
    cudaGetSymbolAddress((void**)&qkv,   g_qkv);
    cudaGetSymbolAddress((void**)&qt,    g_qt);
    cudaGetSymbolAddress((void**)&kt,    g_kt);
    cudaGetSymbolAddress((void**)&vt,    g_vt);
    cudaGetSymbolAddress((void**)&att,   g_att);
    cudaGetSymbolAddress((void**)&att2,  g_att2);
    cudaGetSymbolAddress((void**)&spat,  g_spat);
    cudaGetSymbolAddress((void**)&temp,  g_temp);
    cudaGetSymbolAddress((void**)&cq,    g_cq);
    cudaGetSymbolAddress((void**)&ckv,   g_ckv);
    cudaGetSymbolAddress((void**)&x1,    g_x1);
    cudaGetSymbolAddress((void**)&xm,    g_xm);
    cudaGetSymbolAddress((void**)&y,     g_y);

    cudaFuncSetAttribute(gemm_tc, cudaFuncAttributeMaxDynamicSharedMemorySize, GEMM_SMEM);
    cudaFuncSetAttribute(attn_tc, cudaFuncAttributeMaxDynamicSharedMemorySize, ATT_SMEM);

    rmean_kernel<<<Bc, Dc>>>(x, mean);
    router_kernel<<<Bc, 128>>>(mean, r_w1, r_b1, r_w2, r_b2, idx_s, idx_t);

    ln2_kernel<<<dim3(BTc, 2), 256>>>(x, ns_g, ns_b, xns, nt_g, nt_b, xt);

    // ---- spatial qkv (N=2304 -> 36 y-tiles of 64) ----
    {
        GArgs a = mkargs();
        a.A[0] = xns; a.W[0] = sp_wqkv; a.bias[0] = sp_bqkv; a.C[0] = qkv; a.ldc[0] = 3 * Dc;
        a.wstride[0] = (long)3 * Dc * Dc; a.eidx[0] = idx_s; a.lda[0] = Dc;
        a.nSlices = 1; a.ldw = Dc; a.bstride = 3 * Dc; a.Kdim = Dc; a.act = 0;
        gemm_tc<<<dim3(4, 36, 8), 256, GEMM_SMEM>>>(a);
    }
    attn_tc<<<dim3(8, 8, 8), 128, ATT_SMEM>>>(qkv, 3 * Dc, qkv + Dc, 3 * Dc,
                                              qkv + 2 * Dc, 3 * Dc, att, Dc, 0);
    // ---- spatial Wo ----
    {
        GArgs a = mkargs();
        a.A[0] = att; a.W[0] = sp_wo; a.bias[0] = sp_bo; a.C[0] = spat; a.ldc[0] = Dc;
        a.wstride[0] = (long)Dc * Dc; a.eidx[0] = idx_s; a.lda[0] = Dc;
        a.nSlices = 1; a.ldw = Dc; a.bstride = Dc; a.Kdim = Dc; a.act = 0;
        gemm_tc<<<dim3(4, 12, 8), 256, GEMM_SMEM>>>(a);
    }

    // ---- temporal q/k/v fused (3 slices x 12 y-tiles) ----
    {
        GArgs a = mkargs();
        a.A[0] = xt; a.W[0] = tp_wq; a.bias[0] = tp_bq; a.C[0] = qt; a.ldc[0] = Dc;
        a.wstride[0] = (long)Dc * Dc; a.eidx[0] = idx_t; a.lda[0] = Dc; a.yOff[0] = 0;
        a.A[1] = xt; a.W[1] = tp_wk; a.bias[1] = tp_bk; a.C[1] = kt; a.ldc[1] = Dc;
        a.wstride[1] = (long)Dc * Dc; a.eidx[1] = idx_t; a.lda[1] = Dc; a.yOff[1] = 12;
        a.A[2] = xt; a.W[2] = tp_wv; a.bias[2] = tp_bv; a.C[2] = vt; a.ldc[2] = Dc;
        a.wstride[2] = (long)Dc * Dc; a.eidx[2] = idx_t; a.lda[2] = Dc; a.yOff[2] = 24;
        a.nSlices = 3; a.ldw = Dc; a.bstride = Dc; a.Kdim = Dc; a.act = 0;
        gemm_tc<<<dim3(4, 36, 8), 256, GEMM_SMEM>>>(a);
    }
    attn_tc<<<dim3(8, 8, 8), 128, ATT_SMEM>>>(qt, Dc, kt, Dc, vt, Dc, att2, Dc, 1);
    // ---- temporal Wo (+ xt residual) ----
    {
        GArgs a = mkargs();
        a.A[0] = att2; a.W[0] = tp_wo; a.bias[0] = tp_bo; a.C[0] = temp; a.ldc[0] = Dc;
        a.wstride[0] = (long)Dc * Dc; a.eidx[0] = idx_t; a.lda[0] = Dc; a.resid[0] = xt;
        a.nSlices = 1; a.ldw = Dc; a.bstride = Dc; a.Kdim = Dc; a.act = 0;
        gemm_tc<<<dim3(4, 12, 8), 256, GEMM_SMEM>>>(a);
    }

    // ---- cross qkv fused (3 slices x 12 y-tiles) ----
    {
        GArgs a = mkargs();
        a.A[0] = spat; a.W[0] = c_wqkv;               a.bias[0] = c_bqkv;          a.C[0] = cq;       a.ldc[0] = Dc;     a.lda[0] = Dc; a.yOff[0] = 0;
        a.A[1] = temp; a.W[1] = c_wqkv + Dc * Dc;     a.bias[1] = c_bqkv + Dc;     a.C[1] = ckv;      a.ldc[1] = 2 * Dc; a.lda[1] = Dc; a.yOff[1] = 12;
        a.A[2] = temp; a.W[2] = c_wqkv + 2 * Dc * Dc; a.bias[2] = c_bqkv + 2 * Dc; a.C[2] = ckv + Dc; a.ldc[2] = 2 * Dc; a.lda[2] = Dc; a.yOff[2] = 24;
        a.nSlices = 3; a.ldw = Dc; a.bstride = 0; a.Kdim = Dc; a.act = 0;
        gemm_tc<<<dim3(32, 36, 1), 256, GEMM_SMEM>>>(a);
    }
    attn_tc<<<dim3(8, 8, 8), 128, ATT_SMEM>>>(cq, Dc, ckv, 2 * Dc,
                                              ckv + Dc, 2 * Dc, att, Dc, 0);
    // ---- cross Wo (+ x residual) ----
    {
        GArgs a = mkargs();
        a.A[0] = att; a.W[0] = c_wo; a.bias[0] = c_bo; a.C[0] = x1; a.ldc[0] = Dc;
        a.lda[0] = Dc; a.resid[0] = x;
        a.nSlices = 1; a.ldw = Dc; a.bstride = 0; a.Kdim = Dc; a.act = 0;
        gemm_tc<<<dim3(32, 12, 1), 256, GEMM_SMEM>>>(a);
    }

    // ---- MLP with residual ----
    ln_kernel<<<BTc, 256>>>(x1, nm_g, nm_b, xm);
    {
        GArgs a = mkargs();
        a.A[0] = xm; a.W[0] = m_w1; a.bias[0] = m_b1; a.C[0] = y; a.ldc[0] = 4 * Dc;
        a.lda[0] = Dc;
        a.nSlices = 1; a.ldw = Dc; a.bstride = 0; a.Kdim = Dc; a.act = 1;
        gemm_tc<<<dim3(32, 48, 1), 256, GEMM_SMEM>>>(a);
    }
    {
        GArgs a = mkargs();
        a.A[0] = y; a.W[0] = m_w2; a.bias[0] = m_b2; a.C[0] = out; a.ldc[0] = Dc;
        a.lda[0] = 4 * Dc; a.resid[0] = x1;
        a.nSlices = 1; a.ldw = 4 * Dc; a.bstride = 0; a.Kdim = 4 * Dc; a.act = 0;
        gemm_tc<<<dim3(32, 12, 1), 256, GEMM_SMEM>>>(a);
    }
}

// round 15
// speedup vs baseline: 1.4706x; 1.0189x over previous
#include <cuda_runtime.h>
#include <math.h>
#include <stdint.h>

// Problem constants
#define Bc 8
#define Tc 512
#define Dc 768
#define Hc 8
#define HDc 96
#define BTc (Bc*Tc)

// ---------------- scratch (device globals; no cudaMalloc allowed) ----------------
__device__ __align__(16) float g_mean[Bc*Dc];
__device__ int   g_idx_s[Bc];
__device__ int   g_idx_t[Bc];
__device__ __align__(16) float g_xns [BTc*Dc];
__device__ __align__(16) float g_xt  [BTc*Dc];
__device__ __align__(16) float g_qkv [BTc*3*Dc];
__device__ __align__(16) float g_qt  [BTc*Dc];
__device__ __align__(16) float g_kt  [BTc*Dc];
__device__ __align__(16) float g_vt  [BTc*Dc];
__device__ __align__(16) float g_att [BTc*Dc];
__device__ __align__(16) float g_att2[BTc*Dc];
__device__ __align__(16) float g_spat[BTc*Dc];
__device__ __align__(16) float g_temp[BTc*Dc];
__device__ __align__(16) float g_cq  [BTc*Dc];
__device__ __align__(16) float g_ckv [BTc*2*Dc];
__device__ __align__(16) float g_x1  [BTc*Dc];
__device__ __align__(16) float g_xm  [BTc*Dc];
__device__ __align__(16) float g_y   [BTc*4*Dc];

__device__ __forceinline__ float gelu_exact(float v) {
    return 0.5f * v * (1.0f + erff(v * 0.70710678118654752f));
}

__device__ __forceinline__ void mma_tf32(float* c, const uint32_t* a, const uint32_t* b) {
    asm volatile(
        "mma.sync.aligned.m16n8k8.row.col.f32.tf32.tf32.f32 "
        "{%0,%1,%2,%3}, {%4,%5,%6,%7}, {%8,%9}, {%0,%1,%2,%3};\n"
        : "+f"(c[0]), "+f"(c[1]), "+f"(c[2]), "+f"(c[3])
        : "r"(a[0]), "r"(a[1]), "r"(a[2]), "r"(a[3]),
          "r"(b[0]), "r"(b[1]));
}

__device__ __forceinline__ void cp16(uint32_t saddr, const void* g) {
    asm volatile("cp.async.cg.shared.global [%0], [%1], 16;" :: "r"(saddr), "l"(g));
}
#define CP_COMMIT() asm volatile("cp.async.commit_group;" ::: "memory")
#define CP_WAIT0()  asm volatile("cp.async.wait_group 0;" ::: "memory")

// ---------------- router part 1: mean over T ----------------
__global__ void rmean_kernel(const float* __restrict__ x, float* __restrict__ mean) {
    int b = blockIdx.x;
    int d = threadIdx.x;            // 768 threads
    float s = 0.f;
    const float* xb = x + (long)b * Tc * Dc + d;
    #pragma unroll 8
    for (int t = 0; t < Tc; t++) s += xb[(long)t * Dc];
    mean[b * Dc + d] = s * (1.0f / (float)Tc);
}

// ---------------- router part 2: MLP -> argmax experts ----------------
__global__ void router_kernel(const float* __restrict__ mean,
                              const float* __restrict__ w1, const float* __restrict__ b1,
                              const float* __restrict__ w2, const float* __restrict__ b2,
                              int* __restrict__ idx_s, int* __restrict__ idx_t) {
    int b = blockIdx.x;
    int j = threadIdx.x;            // 128 threads
    __shared__ float h[128];
    __shared__ float lg[8];
    float a = b1[j];
    const float* mb = mean + b * Dc;
    const float* wr = w1 + j * Dc;
    for (int d = 0; d < Dc; d++) a += mb[d] * wr[d];
    h[j] = gelu_exact(a);
    __syncthreads();
    if (j < 8) {
        float a2 = b2[j];
        const float* wrr = w2 + j * 128;
        for (int i = 0; i < 128; i++) a2 += h[i] * wrr[i];
        lg[j] = a2;
    }
    __syncthreads();
    if (j == 0) {
        int bi = 0;
        for (int i = 1; i < 4; i++) if (lg[i] > lg[bi]) bi = i;
        idx_s[b] = bi;
        int bt = 4;
        for (int i = 5; i < 8; i++) if (lg[i] > lg[bt]) bt = i;
        idx_t[b] = bt - 4;
    }
}

// ---------------- LayerNorm over D=768, one row per block, 2 param sets ------
__global__ __launch_bounds__(256)
void ln2_kernel(const float* __restrict__ x,
                const float* __restrict__ g0, const float* __restrict__ b0,
                float* __restrict__ o0,
                const float* __restrict__ g1, const float* __restrict__ b1,
                float* __restrict__ o1) {
    long row = blockIdx.x;
    const float* g   = blockIdx.y ? g1 : g0;
    const float* bet = blockIdx.y ? b1 : b0;
    float* o         = blockIdx.y ? o1 : o0;
    int tid = threadIdx.x;
    const float* xr = x + row * Dc;
    float v0 = xr[tid], v1 = xr[tid + 256], v2 = xr[tid + 512];
    float s  = v0 + v1 + v2;
    float ss = v0 * v0 + v1 * v1 + v2 * v2;
    #pragma unroll
    for (int off = 16; off > 0; off >>= 1) {
        s  += __shfl_xor_sync(0xffffffffu, s,  off);
        ss += __shfl_xor_sync(0xffffffffu, ss, off);
    }
    __shared__ float rs[8], rss[8];
    int lane = tid & 31, wid = tid >> 5;
    if (lane == 0) { rs[wid] = s; rss[wid] = ss; }
    __syncthreads();
    if (tid == 0) {
        float S = 0.f, SS = 0.f;
        for (int i = 0; i < 8; i++) { S += rs[i]; SS += rss[i]; }
        float mean = S * (1.0f / (float)Dc);
        float var  = SS * (1.0f / (float)Dc) - mean * mean;
        rs[0] = mean;
        rss[0] = rsqrtf(var + 1e-5f);
    }
    __syncthreads();
    float mean = rs[0], inv = rss[0];
    float* orow = o + row * Dc;
    orow[tid]       = (v0 - mean) * inv * g[tid]       + bet[tid];
    orow[tid + 256] = (v1 - mean) * inv * g[tid + 256] + bet[tid + 256];
    orow[tid + 512] = (v2 - mean) * inv * g[tid + 512] + bet[tid + 512];
}

__global__ __launch_bounds__(256)
void ln_kernel(const float* __restrict__ x, const float* __restrict__ g,
               const float* __restrict__ bet, float* __restrict__ o) {
    long row = blockIdx.x;
    int tid = threadIdx.x;
    const float* xr = x + row * Dc;
    float v0 = xr[tid], v1 = xr[tid + 256], v2 = xr[tid + 512];
    float s  = v0 + v1 + v2;
    float ss = v0 * v0 + v1 * v1 + v2 * v2;
    #pragma unroll
    for (int off = 16; off > 0; off >>= 1) {
        s  += __shfl_xor_sync(0xffffffffu, s,  off);
        ss += __shfl_xor_sync(0xffffffffu, ss, off);
    }
    __shared__ float rs[8], rss[8];
    int lane = tid & 31, wid = tid >> 5;
    if (lane == 0) { rs[wid] = s; rss[wid] = ss; }
    __syncthreads();
    if (tid == 0) {
        float S = 0.f, SS = 0.f;
        for (int i = 0; i < 8; i++) { S += rs[i]; SS += rss[i]; }
        float mean = S * (1.0f / (float)Dc);
        float var  = SS * (1.0f / (float)Dc) - mean * mean;
        rs[0] = mean;
        rss[0] = rsqrtf(var + 1e-5f);
    }
    __syncthreads();
    float mean = rs[0], inv = rss[0];
    float* orow = o + row * Dc;
    orow[tid]       = (v0 - mean) * inv * g[tid]       + bet[tid];
    orow[tid + 256] = (v1 - mean) * inv * g[tid + 256] + bet[tid + 256];
    orow[tid + 512] = (v2 - mean) * inv * g[tid + 512] + bet[tid + 512];
}

// ------------- tensor-core GEMM: C = act(A @ W^T + bias) [+ resid] ------------
// TF32 mma.sync m16n8k8, fp32 accumulate, raw-fp32-bit operands.
// Tiles 128(M) x 64(N) x 32(K), 2-stage cp.async pipeline (54 KB smem),
// 256 threads = 8 warps in 4(M) x 2(N), warp tile 32x32.
// __launch_bounds__(256,4): 4 CTAs/SM (<=64 regs; occupancy-directed).
struct GArgs {
    const float* A[4];
    const float* W[4];
    const float* bias[4];
    const float* resid[4];
    float* C[4];
    int ldc[4];
    int lda[4];
    long wstride[4];
    const int* eidx[4];
    int yOff[4];
    int nSlices;
    int ldw, bstride;      // bstride < 0 => use ldc[slice] as bias stride
    int Kdim, act;
};

#define GROWS 192                         // 128 A rows + 64 B rows
#define GSTAGE_U32 (GROWS * 36)
#define GEMM_SMEM  (2 * GSTAGE_U32 * 4)   // 55296 B

__global__ __launch_bounds__(256, 4)
void gemm_tc(GArgs g) {
    extern __shared__ uint32_t sm[];
    const uint32_t sb = (uint32_t)__cvta_generic_to_shared(sm);

    const int tid  = threadIdx.x;
    const int wid  = tid >> 5;
    const int lane = tid & 31;
    const int grp  = lane >> 2;        // 0..7
    const int tg   = lane & 3;         // 0..3
    const int warpM = wid & 3;         // 0..3  (32 rows each)
    const int warpN = wid >> 2;        // 0..1  (32 cols each)

    const int y = blockIdx.y;
    int slice = 0;
    #pragma unroll
    for (int i = 1; i < 4; i++)
        if (i < g.nSlices && y >= g.yOff[i]) slice = i;
    const int n0 = (y - g.yOff[slice]) * 64;

    const int bz = blockIdx.z;
    const long rowBase = ((long)bz * gridDim.x + blockIdx.x) * 128;

    const int lda = g.lda[slice];
    const int ldc = g.ldc[slice];
    const int bstr = (g.bstride < 0) ? ldc : g.bstride;
    const int e = g.eidx[slice] ? g.eidx[slice][bz] : 0;
    const float* Ab = g.A[slice] + rowBase * lda;
    const float* Wb = g.W[slice] + (long)e * g.wstride[slice] + (long)n0 * g.ldw;
    const float* bb = g.bias[slice] + (long)e * bstr + n0;
    const float* resid = g.resid[slice];
    float* C = g.C[slice];

    float acc[2][4][4];
    #pragma unroll
    for (int i = 0; i < 2; i++)
        #pragma unroll
        for (int j = 0; j < 4; j++)
            #pragma unroll
            for (int r = 0; r < 4; r++) acc[i][j][r] = 0.f;

    // tile loader: per-thread fixed rows, no conditionals.
    // arow = tid>>3 in [0,32); acol = (tid&7)*4.
    // A rows: arow + 32q, q=0..3 ; B rows: arow + 32q, q=0..1.
    const int ldw_ = g.ldw;
    const int nK = g.Kdim >> 5;
    const int arow = tid >> 3;
    const int acol = (tid & 7) * 4;
    const float* aLd = Ab + (long)arow * lda + acol;
    const float* wLd = Wb + (long)arow * ldw_ + acol;
    const uint32_t sA = sb + (arow * 36 + acol) * 4;          // + q*32*36*4
    const uint32_t sB = sb + ((128 + arow) * 36 + acol) * 4;

    // prologue: stage 0 <- tile 0
    {
        #pragma unroll
        for (int q = 0; q < 4; q++)
            cp16(sA + q * (32 * 36 * 4), aLd + (long)(32 * q) * lda);
        #pragma unroll
        for (int q = 0; q < 2; q++)
            cp16(sB + q * (32 * 36 * 4), wLd + (long)(32 * q) * ldw_);
        CP_COMMIT();
    }

    for (int kt = 0; kt < nK; kt++) {
        CP_WAIT0();
        __syncthreads();

        if (kt + 1 < nK) {
            const uint32_t stoff = ((kt + 1) & 1) * (GSTAGE_U32 * 4);
            const int k0 = (kt + 1) * 32;
            #pragma unroll
            for (int q = 0; q < 4; q++)
                cp16(sA + stoff + q * (32 * 36 * 4), aLd + (long)(32 * q) * lda + k0);
            #pragma unroll
            for (int q = 0; q < 2; q++)
                cp16(sB + stoff + q * (32 * 36 * 4), wLd + (long)(32 * q) * ldw_ + k0);
            CP_COMMIT();
        }

        const uint32_t* Asb = sm + (kt & 1) * GSTAGE_U32;
        const uint32_t* Bsb = Asb + 128 * 36;

        #pragma unroll
        for (int kk = 0; kk < 4; kk++) {
            const int k = kk * 8 + tg;
            uint32_t afr[2][4];
            #pragma unroll
            for (int i = 0; i < 2; i++) {
                const int m = warpM * 32 + i * 16 + grp;
                afr[i][0] = Asb[m * 36 + k];
                afr[i][1] = Asb[(m + 8) * 36 + k];
                afr[i][2] = Asb[m * 36 + k + 4];
                afr[i][3] = Asb[(m + 8) * 36 + k + 4];
            }
            uint32_t bfr[4][2];
            #pragma unroll
            for (int j = 0; j < 4; j++) {
                const int n = warpN * 32 + j * 8 + grp;
                bfr[j][0] = Bsb[n * 36 + k];
                bfr[j][1] = Bsb[n * 36 + k + 4];
            }
            #pragma unroll
            for (int i = 0; i < 2; i++)
                #pragma unroll
                for (int j = 0; j < 4; j++)
                    mma_tf32(acc[i][j], afr[i], bfr[j]);
        }
    }

    #pragma unroll
    for (int i = 0; i < 2; i++) {
        const long m0 = rowBase + warpM * 32 + i * 16 + grp;
        #pragma unroll
        for (int j = 0; j < 4; j++) {
            const int coff = warpN * 32 + j * 8 + 2 * tg;
            const int col = n0 + coff;
            #pragma unroll
            for (int rr = 0; rr < 2; rr++) {
                const long row = m0 + rr * 8;
                float v0 = acc[i][j][rr * 2 + 0] + bb[coff];
                float v1 = acc[i][j][rr * 2 + 1] + bb[coff + 1];
                if (g.act == 1) { v0 = gelu_exact(v0); v1 = gelu_exact(v1); }
                if (resid) {
                    const float* rp = resid + row * ldc + col;
                    v0 += rp[0]; v1 += rp[1];
                }
                *(float2*)(C + row * ldc + col) = make_float2(v0, v1);
            }
        }
    }
}

// ---------- tensor-core flash attention: 64 Q-rows/CTA, 64-col KV tiles ----------
// 128 threads = 4 warps; warp w owns Q rows [16w, 16w+16) -> softmax warp-local.
#define AT_LD  104
#define AT_LDP 72
#define ATT_SMEM ((3*64*AT_LD + 64*AT_LDP) * 4)
__global__ __launch_bounds__(128)
void attn_tc(const float* __restrict__ Qp, int ldq,
             const float* __restrict__ Kp, int ldk,
             const float* __restrict__ Vp, int ldv,
             float* __restrict__ Op, int ldo, int causal) {
    extern __shared__ uint32_t asm_[];
    uint32_t* Qs = asm_;
    uint32_t* Ks = asm_ + 64 * AT_LD;
    uint32_t* Vs = asm_ + 2 * 64 * AT_LD;
    uint32_t* Ps = asm_ + 3 * 64 * AT_LD;

    const int tid  = threadIdx.x;
    const int lane = tid & 31;
    const int w    = tid >> 5;
    const int grp  = lane >> 2;
    const int tg   = lane & 3;
    const int qt = blockIdx.x;
    const int h  = blockIdx.y;
    const int b  = blockIdx.z;
    const float scale = 0.1020620726159658f;   // 1/sqrt(96)

    const float* Qb = Qp + ((long)b * Tc + qt * 64) * ldq + h * HDc;
    const float* Kb = Kp + (long)b * Tc * ldk + h * HDc;
    const float* Vb = Vp + (long)b * Tc * ldv + h * HDc;

    for (int i = tid; i < 64 * 24; i += 128) {
        int r = i / 24, c = (i % 24) * 4;
        *(uint4*)&Qs[r * AT_LD + c] = *(const uint4*)(Qb + (long)r * ldq + c);
    }

    float m_lo = -1e30f, m_hi = -1e30f, l_lo = 0.f, l_hi = 0.f;
    float oacc[12][4];
    #pragma unroll
    for (int d = 0; d < 12; d++)
        #pragma unroll
        for (int r = 0; r < 4; r++) oacc[d][r] = 0.f;

    const int m0 = w * 16 + grp;
    const int rowg_lo = qt * 64 + m0;
    const int rowg_hi = rowg_lo + 8;

    const int ktmax = causal ? qt : (Tc / 64 - 1);
    for (int kt = 0; kt <= ktmax; kt++) {
        __syncthreads();
        for (int i = tid; i < 64 * 24; i += 128) {
            int r = i / 24, c = (i % 24) * 4;
            *(uint4*)&Ks[r * AT_LD + c] = *(const uint4*)(Kb + (long)(kt * 64 + r) * ldk + c);
            *(uint4*)&Vs[r * AT_LD + c] = *(const uint4*)(Vb + (long)(kt * 64 + r) * ldv + c);
        }
        __syncthreads();

        float sacc[8][4];
        #pragma unroll
        for (int j = 0; j < 8; j++)
            #pragma unroll
            for (int r = 0; r < 4; r++) sacc[j][r] = 0.f;

        #pragma unroll
        for (int kk = 0; kk < 12; kk++) {
            const int k = kk * 8 + tg;
            uint32_t a[4];
            a[0] = Qs[m0 * AT_LD + k];
            a[1] = Qs[(m0 + 8) * AT_LD + k];
            a[2] = Qs[m0 * AT_LD + k + 4];
            a[3] = Qs[(m0 + 8) * AT_LD + k + 4];
            #pragma unroll
            for (int j = 0; j < 8; j++) {
                uint32_t bf[2];
                const int n = j * 8 + grp;
                bf[0] = Ks[n * AT_LD + k];
                bf[1] = Ks[n * AT_LD + k + 4];
                mma_tf32(sacc[j], a, bf);
            }
        }

        const bool dmask = causal && (kt == qt);
        float mt_lo = -1e30f, mt_hi = -1e30f;
        #pragma unroll
        for (int j = 0; j < 8; j++) {
            const int c = kt * 64 + j * 8 + 2 * tg;
            float s0 = sacc[j][0] * scale;
            float s1 = sacc[j][1] * scale;
            float s2 = sacc[j][2] * scale;
            float s3 = sacc[j][3] * scale;
            if (dmask) {
                if (c     > rowg_lo) s0 = -1e30f;
                if (c + 1 > rowg_lo) s1 = -1e30f;
                if (c     > rowg_hi) s2 = -1e30f;
                if (c + 1 > rowg_hi) s3 = -1e30f;
            }
            sacc[j][0] = s0; sacc[j][1] = s1; sacc[j][2] = s2; sacc[j][3] = s3;
            mt_lo = fmaxf(mt_lo, fmaxf(s0, s1));
            mt_hi = fmaxf(mt_hi, fmaxf(s2, s3));
        }
        mt_lo = fmaxf(mt_lo, __shfl_xor_sync(0xffffffffu, mt_lo, 1));
        mt_lo = fmaxf(mt_lo, __shfl_xor_sync(0xffffffffu, mt_lo, 2));
        mt_hi = fmaxf(mt_hi, __shfl_xor_sync(0xffffffffu, mt_hi, 1));
        mt_hi = fmaxf(mt_hi, __shfl_xor_sync(0xffffffffu, mt_hi, 2));

        const float mn_lo = fmaxf(m_lo, mt_lo);
        const float mn_hi = fmaxf(m_hi, mt_hi);
        const float al_lo = __expf(m_lo - mn_lo);
        const float al_hi = __expf(m_hi - mn_hi);

        float ps_lo = 0.f, ps_hi = 0.f;
        #pragma unroll
        for (int j = 0; j < 8; j++) {
            const int c = j * 8 + 2 * tg;
            float p0 = __expf(sacc[j][0] - mn_lo);
            float p1 = __expf(sacc[j][1] - mn_lo);
            float p2 = __expf(sacc[j][2] - mn_hi);
            float p3 = __expf(sacc[j][3] - mn_hi);
            ps_lo += p0 + p1;
            ps_hi += p2 + p3;
            Ps[m0 * AT_LDP + c]           = __float_as_uint(p0);
            Ps[m0 * AT_LDP + c + 1]       = __float_as_uint(p1);
            Ps[(m0 + 8) * AT_LDP + c]     = __float_as_uint(p2);
            Ps[(m0 + 8) * AT_LDP + c + 1] = __float_as_uint(p3);
        }
        ps_lo += __shfl_xor_sync(0xffffffffu, ps_lo, 1);
        ps_lo += __shfl_xor_sync(0xffffffffu, ps_lo, 2);
        ps_hi += __shfl_xor_sync(0xffffffffu, ps_hi, 1);
        ps_hi += __shfl_xor_sync(0xffffffffu, ps_hi, 2);

        l_lo = l_lo * al_lo + ps_lo;  m_lo = mn_lo;
        l_hi = l_hi * al_hi + ps_hi;  m_hi = mn_hi;
        #pragma unroll
        for (int d = 0; d < 12; d++) {
            oacc[d][0] *= al_lo; oacc[d][1] *= al_lo;
            oacc[d][2] *= al_hi; oacc[d][3] *= al_hi;
        }
        __syncwarp();

        #pragma unroll
        for (int kc = 0; kc < 8; kc++) {
            const int k = kc * 8 + tg;
            uint32_t a[4];
            a[0] = Ps[m0 * AT_LDP + k];
            a[1] = Ps[(m0 + 8) * AT_LDP + k];
            a[2] = Ps[m0 * AT_LDP + k + 4];
            a[3] = Ps[(m0 + 8) * AT_LDP + k + 4];
            #pragma unroll
            for (int d = 0; d < 12; d++) {
                uint32_t bf[2];
                const int n = d * 8 + grp;
                bf[0] = Vs[k * AT_LD + n];
                bf[1] = Vs[(k + 4) * AT_LD + n];
                mma_tf32(oacc[d], a, bf);
            }
        }
    }

    const float inv_lo = 1.0f / l_lo;
    const float inv_hi = 1.0f / l_hi;
    float* Ob = Op + ((long)b * Tc + qt * 64 + w * 16) * ldo + h * HDc;
    #pragma unroll
    for (int d = 0; d < 12; d++) {
        const int c = d * 8 + 2 * tg;
        *(float2*)(Ob + (long)grp * ldo + c) =
            make_float2(oacc[d][0] * inv_lo, oacc[d][1] * inv_lo);
        *(float2*)(Ob + (long)(grp + 8) * ldo + c) =
            make_float2(oacc[d][2] * inv_hi, oacc[d][3] * inv_hi);
    }
}

// ---------------- host driver ----------------
static GArgs mkargs() {
    GArgs g;
    for (int i = 0; i < 4; i++) {
        g.A[i]=0; g.W[i]=0; g.bias[i]=0; g.resid[i]=0; g.C[i]=0;
        g.ldc[i]=0; g.lda[i]=0; g.wstride[i]=0; g.eidx[i]=0; g.yOff[i]=0;
    }
    g.nSlices=1; g.ldw=0; g.bstride=0; g.Kdim=0; g.act=0;
    return g;
}

extern "C" void kernel_launch(void* const* d_in, const int* in_sizes, int n_in,
                              void* d_out, int out_size) {
    (void)in_sizes; (void)n_in; (void)out_size;
    const float* x       = (const float*)d_in[0];
    const float* r_w1    = (const float*)d_in[1];
    const float* r_b1    = (const float*)d_in[2];
    const float* r_w2    = (const float*)d_in[3];
    const float* r_b2    = (const float*)d_in[4];
    const float* ns_g    = (const float*)d_in[5];
    const float* ns_b    = (const float*)d_in[6];
    const float* nt_g    = (const float*)d_in[7];
    const float* nt_b    = (const float*)d_in[8];
    const float* nm_g    = (const float*)d_in[9];
    const float* nm_b    = (const float*)d_in[10];
    const float* sp_wqkv = (const float*)d_in[11];
    const float* sp_bqkv = (const float*)d_in[12];
    const float* sp_wo   = (const float*)d_in[13];
    const float* sp_bo   = (const float*)d_in[14];
    const float* tp_wq   = (const float*)d_in[15];
    const float* tp_bq   = (const float*)d_in[16];
    const float* tp_wk   = (const float*)d_in[17];
    const float* tp_bk   = (const float*)d_in[18];
    const float* tp_wv   = (const float*)d_in[19];
    const float* tp_bv   = (const float*)d_in[20];
    const float* tp_wo   = (const float*)d_in[21];
    const float* tp_bo   = (const float*)d_in[22];
    const float* c_wqkv  = (const float*)d_in[23];
    const float* c_bqkv  = (const float*)d_in[24];
    const float* c_wo    = (const float*)d_in[25];
    const float* c_bo    = (const float*)d_in[26];
    const float* m_w1    = (const float*)d_in[27];
    const float* m_b1    = (const float*)d_in[28];
    const float* m_w2    = (const float*)d_in[29];
    const float* m_b2    = (const float*)d_in[30];
    float* out = (float*)d_out;

    float *mean, *xns, *xt, *qkv, *qt, *kt, *vt, *att, *att2, *spat, *temp, *cq, *ckv, *x1, *xm, *y;
    int *idx_s, *idx_t;
    cudaGetSymbolAddress((void**)&mean,  g_mean);
    cudaGetSymbolAddress((void**)&idx_s, g_idx_s);
    cudaGetSymbolAddress((void**)&idx_t, g_idx_t);
    cudaGetSymbolAddress((void**)&xns,   g_xns);
    cudaGetSymbolAddress((void**)&xt,    g_xt);
    cudaGetSymbolAddress((void**)&qkv,   g_qkv);
    cudaGetSymbolAddress((void**)&qt,    g_qt);
    cudaGetSymbolAddress((void**)&kt,    g_kt);
    cudaGetSymbolAddress((void**)&vt,    g_vt);
    cudaGetSymbolAddress((void**)&att,   g_att);
    cudaGetSymbolAddress((void**)&att2,  g_att2);
    cudaGetSymbolAddress((void**)&spat,  g_spat);
    cudaGetSymbolAddress((void**)&temp,  g_temp);
    cudaGetSymbolAddress((void**)&cq,    g_cq);
    cudaGetSymbolAddress((void**)&ckv,   g_ckv);
    cudaGetSymbolAddress((void**)&x1,    g_x1);
    cudaGetSymbolAddress((void**)&xm,    g_xm);
    cudaGetSymbolAddress((void**)&y,     g_y);

    cudaFuncSetAttribute(gemm_tc, cudaFuncAttributeMaxDynamicSharedMemorySize, GEMM_SMEM);
    cudaFuncSetAttribute(attn_tc, cudaFuncAttributeMaxDynamicSharedMemorySize, ATT_SMEM);

    rmean_kernel<<<Bc, Dc>>>(x, mean);
    router_kernel<<<Bc, 128>>>(mean, r_w1, r_b1, r_w2, r_b2, idx_s, idx_t);

    ln2_kernel<<<dim3(BTc, 2), 256>>>(x, ns_g, ns_b, xns, nt_g, nt_b, xt);

    // ---- spatial qkv (N=2304 -> 36 y-tiles of 64) ----
    {
        GArgs a = mkargs();
        a.A[0] = xns; a.W[0] = sp_wqkv; a.bias[0] = sp_bqkv; a.C[0] = qkv; a.ldc[0] = 3 * Dc;
        a.wstride[0] = (long)3 * Dc * Dc; a.eidx[0] = idx_s; a.lda[0] = Dc;
        a.nSlices = 1; a.ldw = Dc; a.bstride = 3 * Dc; a.Kdim = Dc; a.act = 0;
        gemm_tc<<<dim3(4, 36, 8), 256, GEMM_SMEM>>>(a);
    }
    attn_tc<<<dim3(8, 8, 8), 128, ATT_SMEM>>>(qkv, 3 * Dc, qkv + Dc, 3 * Dc,
                                              qkv + 2 * Dc, 3 * Dc, att, Dc, 0);
    // ---- spatial Wo ----
    {
        GArgs a = mkargs();
        a.A[0] = att; a.W[0] = sp_wo; a.bias[0] = sp_bo; a.C[0] = spat; a.ldc[0] = Dc;
        a.wstride[0] = (long)Dc * Dc; a.eidx[0] = idx_s; a.lda[0] = Dc;
        a.nSlices = 1; a.ldw = Dc; a.bstride = Dc; a.Kdim = Dc; a.act = 0;
        gemm_tc<<<dim3(4, 12, 8), 256, GEMM_SMEM>>>(a);
    }

    // ---- temporal q/k/v fused (3 slices x 12 y-tiles) ----
    {
        GArgs a = mkargs();
        a.A[0] = xt; a.W[0] = tp_wq; a.bias[0] = tp_bq; a.C[0] = qt; a.ldc[0] = Dc;
        a.wstride[0] = (long)Dc * Dc; a.eidx[0] = idx_t; a.lda[0] = Dc; a.yOff[0] = 0;
        a.A[1] = xt; a.W[1] = tp_wk; a.bias[1] = tp_bk; a.C[1] = kt; a.ldc[1] = Dc;
        a.wstride[1] = (long)Dc * Dc; a.eidx[1] = idx_t; a.lda[1] = Dc; a.yOff[1] = 12;
        a.A[2] = xt; a.W[2] = tp_wv; a.bias[2] = tp_bv; a.C[2] = vt; a.ldc[2] = Dc;
        a.wstride[2] = (long)Dc * Dc; a.eidx[2] = idx_t; a.lda[2] = Dc; a.yOff[2] = 24;
        a.nSlices = 3; a.ldw = Dc; a.bstride = Dc; a.Kdim = Dc; a.act = 0;
        gemm_tc<<<dim3(4, 36, 8), 256, GEMM_SMEM>>>(a);
    }
    attn_tc<<<dim3(8, 8, 8), 128, ATT_SMEM>>>(qt, Dc, kt, Dc, vt, Dc, att2, Dc, 1);
    // ---- temporal Wo (+ xt residual) ----
    {
        GArgs a = mkargs();
        a.A[0] = att2; a.W[0] = tp_wo; a.bias[0] = tp_bo; a.C[0] = temp; a.ldc[0] = Dc;
        a.wstride[0] = (long)Dc * Dc; a.eidx[0] = idx_t; a.lda[0] = Dc; a.resid[0] = xt;
        a.nSlices = 1; a.ldw = Dc; a.bstride = Dc; a.Kdim = Dc; a.act = 0;
        gemm_tc<<<dim3(4, 12, 8), 256, GEMM_SMEM>>>(a);
    }

    // ---- cross qkv fused (3 slices x 12 y-tiles) ----
    {
        GArgs a = mkargs();
        a.A[0] = spat; a.W[0] = c_wqkv;               a.bias[0] = c_bqkv;          a.C[0] = cq;       a.ldc[0] = Dc;     a.lda[0] = Dc; a.yOff[0] = 0;
        a.A[1] = temp; a.W[1] = c_wqkv + Dc * Dc;     a.bias[1] = c_bqkv + Dc;     a.C[1] = ckv;      a.ldc[1] = 2 * Dc; a.lda[1] = Dc; a.yOff[1] = 12;
        a.A[2] = temp; a.W[2] = c_wqkv + 2 * Dc * Dc; a.bias[2] = c_bqkv + 2 * Dc; a.C[2] = ckv + Dc; a.ldc[2] = 2 * Dc; a.lda[2] = Dc; a.yOff[2] = 24;
        a.nSlices = 3; a.ldw = Dc; a.bstride = 0; a.Kdim = Dc; a.act = 0;
        gemm_tc<<<dim3(32, 36, 1), 256, GEMM_SMEM>>>(a);
    }
    attn_tc<<<dim3(8, 8, 8), 128, ATT_SMEM>>>(cq, Dc, ckv, 2 * Dc,
                                              ckv + Dc, 2 * Dc, att, Dc, 0);
    // ---- cross Wo (+ x residual) ----
    {
        GArgs a = mkargs();
        a.A[0] = att; a.W[0] = c_wo; a.bias[0] = c_bo; a.C[0] = x1; a.ldc[0] = Dc;
        a.lda[0] = Dc; a.resid[0] = x;
        a.nSlices = 1; a.ldw = Dc; a.bstride = 0; a.Kdim = Dc; a.act = 0;
        gemm_tc<<<dim3(32, 12, 1), 256, GEMM_SMEM>>>(a);
    }

    // ---- MLP with residual ----
    ln_kernel<<<BTc, 256>>>(x1, nm_g, nm_b, xm);
    {
        GArgs a = mkargs();
        a.A[0] = xm; a.W[0] = m_w1; a.bias[0] = m_b1; a.C[0] = y; a.ldc[0] = 4 * Dc;
        a.lda[0] = Dc;
        a.nSlices = 1; a.ldw = Dc; a.bstride = 0; a.Kdim = Dc; a.act = 1;
        gemm_tc<<<dim3(32, 48, 1), 256, GEMM_SMEM>>>(a);
    }
    {
        GArgs a = mkargs();
        a.A[0] = y; a.W[0] = m_w2; a.bias[0] = m_b2; a.C[0] = out; a.ldc[0] = Dc;
        a.lda[0] = 4 * Dc; a.resid[0] = x1;
        a.nSlices = 1; a.ldw = 4 * Dc; a.bstride = 0; a.Kdim = 4 * Dc; a.act = 0;
        gemm_tc<<<dim3(32, 12, 1), 256, GEMM_SMEM>>>(a);
    }
}